// round 3
// baseline (speedup 1.0000x reference)
#include <cuda_runtime.h>
#include <math.h>

#define Bn 4
#define Tn 4096
#define Cn 2048
#define HD 128
#define Mn (Bn*Tn)

// scratch (allowed: __device__ globals, no runtime allocation)
__device__ float g_Q[(size_t)Mn*HD];
__device__ float g_K[(size_t)Mn*HD];
__device__ float g_V[(size_t)Mn*HD];

// ---------------------------------------------------------------------------
// Kernel 1: QKV projection + RoPE (+ score scale folded into Q)
// grid (Mn/64, 1, 3), block 256.  z=0:Q  z=1:K  z=2:V
// ---------------------------------------------------------------------------
__global__ __launch_bounds__(256) void proj_kernel(
    const float* __restrict__ x,  const float* __restrict__ Wq,
    const float* __restrict__ Wk, const float* __restrict__ Wv,
    const float* __restrict__ cs, const float* __restrict__ sn)
{
    const int z = blockIdx.z;
    const float* __restrict__ W = (z == 0) ? Wq : (z == 1 ? Wk : Wv);
    float* __restrict__ Out = (z == 0) ? g_Q : (z == 1 ? g_K : g_V);
    const int m0 = blockIdx.x * 64;

    __shared__ float As[32][65];    // [k][m], pad 65 -> conflict-free stores
    __shared__ float Bs[32][128];   // [k][d]

    const int tid = threadIdx.x;
    const int tx = tid & 31;        // 0..31 -> cols tx*4..+3
    const int ty = tid >> 5;        // 0..7  -> rows ty + i*8

    float acc[8][4];
    #pragma unroll
    for (int i = 0; i < 8; i++)
        #pragma unroll
        for (int j = 0; j < 4; j++) acc[i][j] = 0.f;

    const int dW  = tid >> 1;          // 0..127
    const int khW = (tid & 1) * 16;    // 0 or 16

    for (int k0 = 0; k0 < Cn; k0 += 32) {
        // x tile: coalesced 128B rows, transposed store (stride 65 -> no conflict)
        #pragma unroll
        for (int p = 0; p < 8; p++) {
            int r = p * 8 + ty;
            As[tx][r] = x[(m0 + r) * Cn + k0 + tx];
        }
        // W tile: W[d][k], each thread 16 contiguous k via 4 float4
        #pragma unroll
        for (int q = 0; q < 4; q++) {
            float4 w = *(const float4*)&W[dW * Cn + k0 + khW + q * 4];
            Bs[khW + q*4 + 0][dW] = w.x;
            Bs[khW + q*4 + 1][dW] = w.y;
            Bs[khW + q*4 + 2][dW] = w.z;
            Bs[khW + q*4 + 3][dW] = w.w;
        }
        __syncthreads();

        #pragma unroll
        for (int k = 0; k < 32; k++) {
            float4 b = *(const float4*)&Bs[k][tx * 4];
            #pragma unroll
            for (int i = 0; i < 8; i++) {
                float a = As[k][ty + i * 8];   // warp-broadcast
                acc[i][0] += a * b.x;
                acc[i][1] += a * b.y;
                acc[i][2] += a * b.z;
                acc[i][3] += a * b.w;
            }
        }
        __syncthreads();
    }

    // epilogue: RoPE on Q/K, score scale on Q
    const float scale = 0.022097086912079608f;  // 1/sqrt(2048) = C^-0.5
    #pragma unroll
    for (int i = 0; i < 8; i++) {
        int m = m0 + ty + i * 8;
        int t = m & (Tn - 1);
        float4 o;
        if (z < 2) {
            float c0 = cs[t * 64 + tx * 2],     s0 = sn[t * 64 + tx * 2];
            float c1 = cs[t * 64 + tx * 2 + 1], s1 = sn[t * 64 + tx * 2 + 1];
            o.x = acc[i][0] * c0 - acc[i][1] * s0;
            o.y = acc[i][0] * s0 + acc[i][1] * c0;
            o.z = acc[i][2] * c1 - acc[i][3] * s1;
            o.w = acc[i][2] * s1 + acc[i][3] * c1;
            if (z == 0) { o.x *= scale; o.y *= scale; o.z *= scale; o.w *= scale; }
        } else {
            o.x = acc[i][0]; o.y = acc[i][1]; o.z = acc[i][2]; o.w = acc[i][3];
        }
        *(float4*)&Out[m * HD + tx * 4] = o;
    }
}

// ---------------------------------------------------------------------------
// Kernel 2: causal flash attention, fp32, online softmax
// grid (Tn/64, Bn), block 256, dynamic smem ~117KB
// ---------------------------------------------------------------------------
#define PADR 132                    // row pad (floats): 528B, 16B-aligned, low conflicts
#define PADP 68
#define OFF_Q 0
#define OFF_K (64 * PADR)
#define OFF_V (2 * 64 * PADR)
#define OFF_P (3 * 64 * PADR)
#define OFF_M (OFF_P + 64 * PADP)
#define OFF_L (OFF_M + 64)
#define OFF_S (OFF_L + 64)
#define SMEM_FLOATS (OFF_S + 64)
#define SMEM_BYTES  (SMEM_FLOATS * 4)

__global__ __launch_bounds__(256) void flash_kernel(float* __restrict__ out)
{
    extern __shared__ float sm[];
    float* Qs    = sm + OFF_Q;
    float* Ks    = sm + OFF_K;
    float* Vs    = sm + OFF_V;
    float* Ps    = sm + OFF_P;
    float* m_sh  = sm + OFF_M;
    float* l_sh  = sm + OFF_L;
    float* sc_sh = sm + OFF_S;

    const int b   = blockIdx.y;
    const int qt  = gridDim.x - 1 - blockIdx.x;   // heavy tiles first
    const int q0  = qt * 64;
    const int tid = threadIdx.x;

    const int lr = tid >> 5;            // loader row base 0..7
    const int lc = (tid & 31) * 4;      // loader col (float4)

    // load Q tile (resident whole block)
    #pragma unroll
    for (int p = 0; p < 8; p++) {
        float4 v = *(const float4*)&g_Q[(b * Tn + q0 + lr + p * 8) * HD + lc];
        *(float4*)&Qs[(lr + p * 8) * PADR + lc] = v;
    }
    if (tid < 64) { m_sh[tid] = -INFINITY; l_sh[tid] = 0.f; }

    // S-phase coords: 4x4 tile; rows sy*4+i, cols sx*4+j
    const int sy = tid >> 4;            // 0..15
    const int sx = tid & 15;            // 0..15
    // O-phase coords: 8x4 tile; rows oy+i*8, cols ox*4..+3
    const int oy = tid >> 5;            // 0..7
    const int ox = tid & 31;            // 0..31

    float o_acc[8][4];
    #pragma unroll
    for (int i = 0; i < 8; i++)
        #pragma unroll
        for (int j = 0; j < 4; j++) o_acc[i][j] = 0.f;

    for (int kt = 0; kt <= qt; kt++) {
        const int k0 = kt * 64;
        // load K, V tiles (coalesced, conflict-free stores)
        #pragma unroll
        for (int p = 0; p < 8; p++) {
            int g = (b * Tn + k0 + lr + p * 8) * HD + lc;
            *(float4*)&Ks[(lr + p * 8) * PADR + lc] = *(const float4*)&g_K[g];
            *(float4*)&Vs[(lr + p * 8) * PADR + lc] = *(const float4*)&g_V[g];
        }
        __syncthreads();

        // ---- S = Q K^T (Q already carries the C^-0.5 scale) ----
        float s[4][4];
        #pragma unroll
        for (int i = 0; i < 4; i++)
            #pragma unroll
            for (int j = 0; j < 4; j++) s[i][j] = 0.f;

        #pragma unroll 8
        for (int d = 0; d < HD; d += 4) {
            float4 qv[4], kv[4];
            #pragma unroll
            for (int i = 0; i < 4; i++)
                qv[i] = *(const float4*)&Qs[(sy * 4 + i) * PADR + d];
            #pragma unroll
            for (int j = 0; j < 4; j++)
                kv[j] = *(const float4*)&Ks[(sx * 4 + j) * PADR + d];
            #pragma unroll
            for (int i = 0; i < 4; i++)
                #pragma unroll
                for (int j = 0; j < 4; j++)
                    s[i][j] += qv[i].x * kv[j].x + qv[i].y * kv[j].y
                             + qv[i].z * kv[j].z + qv[i].w * kv[j].w;
        }

        // causal mask (only the diagonal tile has masked entries)
        if (kt == qt) {
            #pragma unroll
            for (int i = 0; i < 4; i++)
                #pragma unroll
                for (int j = 0; j < 4; j++)
                    if (k0 + sx * 4 + j > q0 + sy * 4 + i) s[i][j] = -INFINITY;
        }

        // ---- online softmax (row reduce over 16 sx threads) ----
        #pragma unroll
        for (int i = 0; i < 4; i++) {
            int row = sy * 4 + i;
            float mx = fmaxf(fmaxf(s[i][0], s[i][1]), fmaxf(s[i][2], s[i][3]));
            #pragma unroll
            for (int w = 1; w < 16; w <<= 1)
                mx = fmaxf(mx, __shfl_xor_sync(0xffffffffu, mx, w));
            float m_old = m_sh[row];
            float m_new = fmaxf(m_old, mx);
            float p0 = __expf(s[i][0] - m_new);
            float p1 = __expf(s[i][1] - m_new);
            float p2 = __expf(s[i][2] - m_new);
            float p3 = __expf(s[i][3] - m_new);
            float rs = p0 + p1 + p2 + p3;
            #pragma unroll
            for (int w = 1; w < 16; w <<= 1)
                rs += __shfl_xor_sync(0xffffffffu, rs, w);
            Ps[row * PADP + sx * 4 + 0] = p0;
            Ps[row * PADP + sx * 4 + 1] = p1;
            Ps[row * PADP + sx * 4 + 2] = p2;
            Ps[row * PADP + sx * 4 + 3] = p3;
            if (sx == 0) {
                float corr = __expf(m_old - m_new);
                m_sh[row]  = m_new;
                l_sh[row]  = l_sh[row] * corr + rs;
                sc_sh[row] = corr;
            }
        }
        __syncthreads();

        // ---- O = O*corr + P V ----
        #pragma unroll
        for (int i = 0; i < 8; i++) {
            float corr = sc_sh[oy + i * 8];
            o_acc[i][0] *= corr; o_acc[i][1] *= corr;
            o_acc[i][2] *= corr; o_acc[i][3] *= corr;
        }
        #pragma unroll 4
        for (int kj = 0; kj < 64; kj++) {
            float4 v = *(const float4*)&Vs[kj * PADR + ox * 4];
            #pragma unroll
            for (int i = 0; i < 8; i++) {
                float p = Ps[(oy + i * 8) * PADP + kj];   // warp-broadcast
                o_acc[i][0] += p * v.x;
                o_acc[i][1] += p * v.y;
                o_acc[i][2] += p * v.z;
                o_acc[i][3] += p * v.w;
            }
        }
        __syncthreads();   // protect Ks/Vs before next load
    }

    // normalize and write out
    #pragma unroll
    for (int i = 0; i < 8; i++) {
        int r = oy + i * 8;
        float inv = 1.f / l_sh[r];
        float4 o;
        o.x = o_acc[i][0] * inv;
        o.y = o_acc[i][1] * inv;
        o.z = o_acc[i][2] * inv;
        o.w = o_acc[i][3] * inv;
        *(float4*)&out[(b * Tn + q0 + r) * HD + ox * 4] = o;
    }
}

// ---------------------------------------------------------------------------
extern "C" void kernel_launch(void* const* d_in, const int* in_sizes, int n_in,
                              void* d_out, int out_size)
{
    const float* x  = (const float*)d_in[0];
    const float* Wq = (const float*)d_in[1];
    const float* Wk = (const float*)d_in[2];
    const float* Wv = (const float*)d_in[3];
    const float* cs = (const float*)d_in[4];
    const float* sn = (const float*)d_in[5];
    float* out = (float*)d_out;

    cudaFuncSetAttribute(flash_kernel,
                         cudaFuncAttributeMaxDynamicSharedMemorySize, SMEM_BYTES);

    proj_kernel<<<dim3(Mn / 64, 1, 3), 256>>>(x, Wq, Wk, Wv, cs, sn);
    flash_kernel<<<dim3(Tn / 64, Bn), 256, SMEM_BYTES>>>(out);
}

// round 8
// speedup vs baseline: 1.5328x; 1.5328x over previous
#include <cuda_runtime.h>
#include <cuda_bf16.h>
#include <math.h>
#include <stdint.h>

#define Bn 4
#define Tn 4096
#define Cn 2048
#define HD 128
#define Mn (Bn*Tn)
#define SCALE 0.022097086912079608f   // 1/sqrt(2048)

// ---------------- device scratch (static, no runtime alloc) ----------------
__device__ __nv_bfloat16 g_xh[(size_t)Mn*Cn];   // 64 MiB
__device__ __nv_bfloat16 g_xl[(size_t)Mn*Cn];   // 64 MiB
__device__ __nv_bfloat16 g_wh[3*HD*Cn];
__device__ __nv_bfloat16 g_wl[3*HD*Cn];
__device__ float g_Q[(size_t)Mn*HD];
__device__ float g_K[(size_t)Mn*HD];
__device__ float g_V[(size_t)Mn*HD];
__device__ int   g_ctr;

// ---------------- base-ISA PTX helpers (sm_80+ features only) ---------------
__device__ __forceinline__ unsigned smem_u32(const void* p) {
    unsigned a;
    asm("{ .reg .u64 t; cvta.to.shared.u64 t, %1; cvt.u32.u64 %0, t; }" : "=r"(a) : "l"(p));
    return a;
}
#define CP16(dst, src) \
    asm volatile("cp.async.cg.shared.global [%0], [%1], 16;" \
                 :: "r"(dst), "l"(__cvta_generic_to_global((const void*)(src))) : "memory")
#define CP_COMMIT()  asm volatile("cp.async.commit_group;" ::: "memory")
#define CP_WAIT1()   asm volatile("cp.async.wait_group 1;" ::: "memory")
#define CP_WAIT0()   asm volatile("cp.async.wait_group 0;" ::: "memory")

__device__ __forceinline__ void ldsm4(unsigned& r0, unsigned& r1, unsigned& r2, unsigned& r3,
                                      unsigned addr) {
    asm volatile("ldmatrix.sync.aligned.m8n8.x4.shared.b16 {%0,%1,%2,%3}, [%4];"
                 : "=r"(r0), "=r"(r1), "=r"(r2), "=r"(r3) : "r"(addr));
}
__device__ __forceinline__ void mma16816(float* c, const unsigned* a, unsigned b0, unsigned b1) {
    asm volatile(
        "mma.sync.aligned.m16n8k16.row.col.f32.bf16.bf16.f32 "
        "{%0,%1,%2,%3},{%4,%5,%6,%7},{%8,%9},{%0,%1,%2,%3};"
        : "+f"(c[0]), "+f"(c[1]), "+f"(c[2]), "+f"(c[3])
        : "r"(a[0]), "r"(a[1]), "r"(a[2]), "r"(a[3]), "r"(b0), "r"(b1));
}

// ---------------------------------------------------------------------------
// split fp32 -> bf16 hi + bf16 lo
// ---------------------------------------------------------------------------
__global__ void split_kernel(const float* __restrict__ src, int sel, size_t off, int n4)
{
    int i = blockIdx.x * blockDim.x + threadIdx.x;
    if (i >= n4) return;
    __nv_bfloat16* hi = (sel == 0 ? g_xh : g_wh) + off;
    __nv_bfloat16* lo = (sel == 0 ? g_xl : g_wl) + off;
    float4 v = ((const float4*)src)[i];
    __nv_bfloat16 h0 = __float2bfloat16(v.x), h1 = __float2bfloat16(v.y);
    __nv_bfloat16 h2 = __float2bfloat16(v.z), h3 = __float2bfloat16(v.w);
    __nv_bfloat16 l0 = __float2bfloat16(v.x - __bfloat162float(h0));
    __nv_bfloat16 l1 = __float2bfloat16(v.y - __bfloat162float(h1));
    __nv_bfloat16 l2 = __float2bfloat16(v.z - __bfloat162float(h2));
    __nv_bfloat16 l3 = __float2bfloat16(v.w - __bfloat162float(h3));
    ((__nv_bfloat162*)hi)[i*2]   = __halves2bfloat162(h0, h1);
    ((__nv_bfloat162*)hi)[i*2+1] = __halves2bfloat162(h2, h3);
    ((__nv_bfloat162*)lo)[i*2]   = __halves2bfloat162(l0, l1);
    ((__nv_bfloat162*)lo)[i*2+1] = __halves2bfloat162(l2, l3);
}

__global__ void zero_ctr_kernel() { g_ctr = 0; }

// ---------------------------------------------------------------------------
// mma.sync projection GEMM: D[128,128] = (Ah+Al)[128,2048] . (Bh+Bl)[128,2048]^T
// grid (3, 128), 256 threads (8 warps: 4 m-groups x 2 n-groups)
// smem: 2 stages x (Ah|Al|Bh|Bl), each tile 128 rows x 32 bf16 (64B rows)
// swizzle: 16B granule g' = g ^ ((row>>1)&3)  -> conflict-free ldmatrix
// ---------------------------------------------------------------------------
#define TILE_B   8192            // 128 * 64B
#define STAGE_B  (4*TILE_B)      // 32KB
#define GEMM_SMEM (2*STAGE_B)    // 64KB

__device__ __forceinline__ unsigned ldsm_addr(unsigned tile_base, int row0, int kg0, int lane) {
    int r  = row0 + (lane & 7) + ((lane >> 3) & 1) * 8;
    int kg = kg0 + (lane >> 4);
    return tile_base + r * 64 + (((unsigned)(kg ^ ((r >> 1) & 3))) << 4);
}

__global__ __launch_bounds__(256, 1) void gemm_kernel(const float* __restrict__ cs,
                                                      const float* __restrict__ sn)
{
    extern __shared__ char gsm[];
    const int tid  = threadIdx.x;
    const int wid  = tid >> 5;
    const int lane = tid & 31;
    const int z    = blockIdx.x;
    const int m0   = blockIdx.y * 128;
    const unsigned sbase = smem_u32(gsm);

    const __nv_bfloat16* Ah = g_xh + (size_t)m0 * Cn;
    const __nv_bfloat16* Al = g_xl + (size_t)m0 * Cn;
    const __nv_bfloat16* Bh = g_wh + (size_t)z * HD * Cn;
    const __nv_bfloat16* Bl = g_wl + (size_t)z * HD * Cn;

    const int lrow = tid >> 2;          // loader row 0..63 (x2 -> 0..127)
    const int lg   = tid & 3;           // granule

    // issue loads for one chunk into a stage
    #define LOAD_CHUNK(cc, soff)                                                  \
    {                                                                             \
        int k0 = (cc) * 32;                                                       \
        _Pragma("unroll")                                                         \
        for (int q = 0; q < 2; q++) {                                             \
            int row = lrow + q * 64;                                              \
            unsigned d = (soff) + row * 64 + (((unsigned)(lg ^ ((row>>1)&3)))<<4);\
            size_t so = (size_t)row * Cn + k0 + lg * 8;                           \
            CP16(sbase + d + 0*TILE_B, Ah + so);                                  \
            CP16(sbase + d + 1*TILE_B, Al + so);                                  \
            CP16(sbase + d + 2*TILE_B, Bh + so);                                  \
            CP16(sbase + d + 3*TILE_B, Bl + so);                                  \
        }                                                                         \
        CP_COMMIT();                                                              \
    }

    const int wm = wid & 3;             // m group: 32 rows
    const int wn = wid >> 2;            // n group: 64 cols
    const int mrow0 = wm * 32;
    const int nrow0 = wn * 64;

    float c[2][8][4];
    #pragma unroll
    for (int a = 0; a < 2; a++)
        #pragma unroll
        for (int b = 0; b < 8; b++)
            #pragma unroll
            for (int d = 0; d < 4; d++) c[a][b][d] = 0.f;

    LOAD_CHUNK(0, 0u);

    for (int ch = 0; ch < 64; ch++) {
        const unsigned st = (ch & 1) * STAGE_B;
        if (ch + 1 < 64) { LOAD_CHUNK(ch + 1, (unsigned)(((ch + 1) & 1) * STAGE_B)); CP_WAIT1(); }
        else             { CP_WAIT0(); }
        __syncthreads();

        #pragma unroll
        for (int ks = 0; ks < 2; ks++) {
            const int kg0 = ks * 2;
            unsigned ah[2][4], al[2][4], bh[4][4], bl[4][4];
            #pragma unroll
            for (int mt = 0; mt < 2; mt++) {
                unsigned aA = ldsm_addr(sbase + st + 0*TILE_B, mrow0 + mt*16, kg0, lane);
                unsigned aL = ldsm_addr(sbase + st + 1*TILE_B, mrow0 + mt*16, kg0, lane);
                ldsm4(ah[mt][0], ah[mt][1], ah[mt][2], ah[mt][3], aA);
                ldsm4(al[mt][0], al[mt][1], al[mt][2], al[mt][3], aL);
            }
            #pragma unroll
            for (int np = 0; np < 4; np++) {
                unsigned aB = ldsm_addr(sbase + st + 2*TILE_B, nrow0 + np*16, kg0, lane);
                unsigned aC = ldsm_addr(sbase + st + 3*TILE_B, nrow0 + np*16, kg0, lane);
                ldsm4(bh[np][0], bh[np][1], bh[np][2], bh[np][3], aB);
                ldsm4(bl[np][0], bl[np][1], bl[np][2], bl[np][3], aC);
            }
            #pragma unroll
            for (int mt = 0; mt < 2; mt++)
                #pragma unroll
                for (int np = 0; np < 4; np++) {
                    // n-subtile 0: regs {r0, r2};  n-subtile 1: regs {r1, r3}
                    mma16816(c[mt][np*2],   ah[mt], bh[np][0], bh[np][2]);
                    mma16816(c[mt][np*2],   ah[mt], bl[np][0], bl[np][2]);
                    mma16816(c[mt][np*2],   al[mt], bh[np][0], bh[np][2]);
                    mma16816(c[mt][np*2+1], ah[mt], bh[np][1], bh[np][3]);
                    mma16816(c[mt][np*2+1], ah[mt], bl[np][1], bl[np][3]);
                    mma16816(c[mt][np*2+1], al[mt], bh[np][1], bh[np][3]);
                }
        }
        __syncthreads();
    }

    // epilogue: RoPE on Q/K (+ scale on Q); fragment: lane = (g = l>>2, t2 = l&3)
    float* Out = (z == 0) ? g_Q : (z == 1 ? g_K : g_V);
    const int g  = lane >> 2;
    const int t2 = lane & 3;
    #pragma unroll
    for (int mt = 0; mt < 2; mt++) {
        int mA = m0 + mrow0 + mt * 16 + g;      // rows mA, mA+8
        int tA = mA & (Tn - 1);
        #pragma unroll
        for (int nt = 0; nt < 8; nt++) {
            int col = nrow0 + nt * 8 + t2 * 2;  // even col -> RoPE pair
            float v0 = c[mt][nt][0], v1 = c[mt][nt][1];
            float v2 = c[mt][nt][2], v3 = c[mt][nt][3];
            if (z < 2) {
                int j = col >> 1;
                float c0 = cs[tA*64 + j],     s0 = sn[tA*64 + j];
                float c1 = cs[(tA+8)*64 + j], s1 = sn[(tA+8)*64 + j];
                float r0 = v0*c0 - v1*s0, i0 = v0*s0 + v1*c0;
                float r1 = v2*c1 - v3*s1, i1 = v2*s1 + v3*c1;
                if (z == 0) { r0 *= SCALE; i0 *= SCALE; r1 *= SCALE; i1 *= SCALE; }
                v0 = r0; v1 = i0; v2 = r1; v3 = i1;
            }
            *(float2*)&Out[(size_t)mA * HD + col]       = make_float2(v0, v1);
            *(float2*)&Out[(size_t)(mA + 8) * HD + col] = make_float2(v2, v3);
        }
    }
}

// ---------------------------------------------------------------------------
// Flash attention fp32: warp-private softmax stats, smem = 114688B (2 CTA/SM)
// ---------------------------------------------------------------------------
#define OFF_Q 0
#define OFF_K (64*128)
#define OFF_V (2*64*128)
#define OFF_P (3*64*128)            // 64 x 64 floats (Ps[0] doubles as task slot)
#define FLASH_FLOATS (OFF_P + 64*64)    // 28672 floats = 114688 B = 14 x 8KB
#define FLASH_SMEM (FLASH_FLOATS * 4)
#define NTASKS (Bn * (Tn/64))       // 256

// conflict-free XOR swizzle for 128-float rows (16B granule g ^= (row>>2)&7)
__device__ __forceinline__ int swz(int r, int d) {
    return (r << 7) + ((((d >> 2) ^ ((r >> 2) & 7)) << 2) | (d & 3));
}

__global__ __launch_bounds__(256, 2) void flash_kernel(float* __restrict__ out)
{
    extern __shared__ float sm[];
    float* Qs = sm + OFF_Q;
    float* Ks = sm + OFF_K;
    float* Vs = sm + OFF_V;
    float* Ps = sm + OFF_P;

    const int tid = threadIdx.x;
    const int wid = tid >> 5;
    const int lane = tid & 31;
    const int lr = wid;                 // loader row base
    const int lc = lane * 4;            // loader col (float4)
    const int sy = tid >> 4;            // S-phase rows sy*4+i  (warp w: rows 8w..8w+7)
    const int sx = tid & 15;            // S-phase cols sx*4+j
    const int half = (lane >> 4) << 4;  // 0 or 16 (source half for shfl)

    while (true) {
        if (tid == 0) *(int*)&Ps[0] = atomicAdd(&g_ctr, 1);
        __syncthreads();
        const int task = *(const int*)&Ps[0];
        if (task >= NTASKS) break;
        const int b  = task & 3;
        const int qt = 63 - (task >> 2);   // heavy-first (LPT)
        const int q0 = qt * 64;

        #pragma unroll
        for (int p = 0; p < 8; p++) {
            int r = lr + p * 8;
            *(float4*)&Qs[swz(r, lc)] = *(const float4*)&g_Q[((size_t)b*Tn + q0 + r)*HD + lc];
        }

        float m_st[4], l_st[4];
        #pragma unroll
        for (int i = 0; i < 4; i++) { m_st[i] = -INFINITY; l_st[i] = 0.f; }

        float o_acc[8][4];
        #pragma unroll
        for (int i = 0; i < 8; i++)
            #pragma unroll
            for (int j = 0; j < 4; j++) o_acc[i][j] = 0.f;

        for (int kt = 0; kt <= qt; kt++) {
            const int k0 = kt * 64;
            #pragma unroll
            for (int p = 0; p < 8; p++) {
                int r = lr + p * 8;
                size_t gg = ((size_t)b*Tn + k0 + r)*HD + lc;
                *(float4*)&Ks[swz(r, lc)] = *(const float4*)&g_K[gg];
                *(float4*)&Vs[swz(r, lc)] = *(const float4*)&g_V[gg];
            }
            __syncthreads();

            // ---- S = Q K^T (Q pre-scaled) ----
            float s[4][4];
            #pragma unroll
            for (int i = 0; i < 4; i++)
                #pragma unroll
                for (int j = 0; j < 4; j++) s[i][j] = 0.f;

            #pragma unroll 8
            for (int d = 0; d < HD; d += 4) {
                float4 qv[4], kv[4];
                #pragma unroll
                for (int i = 0; i < 4; i++)
                    qv[i] = *(const float4*)&Qs[swz(sy*4 + i, d)];
                #pragma unroll
                for (int j = 0; j < 4; j++)
                    kv[j] = *(const float4*)&Ks[swz(sx*4 + j, d)];
                #pragma unroll
                for (int i = 0; i < 4; i++)
                    #pragma unroll
                    for (int j = 0; j < 4; j++)
                        s[i][j] += qv[i].x*kv[j].x + qv[i].y*kv[j].y
                                 + qv[i].z*kv[j].z + qv[i].w*kv[j].w;
            }

            if (kt == qt) {
                #pragma unroll
                for (int i = 0; i < 4; i++)
                    #pragma unroll
                    for (int j = 0; j < 4; j++)
                        if (k0 + sx*4 + j > q0 + sy*4 + i) s[i][j] = -INFINITY;
            }

            // ---- online softmax (stats in registers; reduce over 16 sx lanes) ----
            float corr[4];
            #pragma unroll
            for (int i = 0; i < 4; i++) {
                int row = sy*4 + i;
                float mx = fmaxf(fmaxf(s[i][0], s[i][1]), fmaxf(s[i][2], s[i][3]));
                #pragma unroll
                for (int w = 1; w < 16; w <<= 1)
                    mx = fmaxf(mx, __shfl_xor_sync(0xffffffffu, mx, w));
                float m_new = fmaxf(m_st[i], mx);
                float p0 = __expf(s[i][0] - m_new);
                float p1 = __expf(s[i][1] - m_new);
                float p2 = __expf(s[i][2] - m_new);
                float p3 = __expf(s[i][3] - m_new);
                float rs = p0 + p1 + p2 + p3;
                #pragma unroll
                for (int w = 1; w < 16; w <<= 1)
                    rs += __shfl_xor_sync(0xffffffffu, rs, w);
                *(float4*)&Ps[row*64 + sx*4] = make_float4(p0, p1, p2, p3);
                corr[i] = __expf(m_st[i] - m_new);
                m_st[i] = m_new;
                l_st[i] = l_st[i] * corr[i] + rs;
            }
            __syncwarp();   // P rows 8w..8w+7 produced & consumed by the same warp

            // ---- O = O*corr + P V   (rows 8*wid + i', cols lane*4..+3) ----
            #pragma unroll
            for (int i = 0; i < 8; i++) {
                float cr = __shfl_sync(0xffffffffu, corr[i & 3], (i >> 2) << 4);
                o_acc[i][0] *= cr; o_acc[i][1] *= cr;
                o_acc[i][2] *= cr; o_acc[i][3] *= cr;
            }
            #pragma unroll 2
            for (int k4 = 0; k4 < 16; k4++) {
                float4 vv[4];
                #pragma unroll
                for (int j = 0; j < 4; j++)
                    vv[j] = *(const float4*)&Vs[swz(k4*4 + j, lane*4)];
                #pragma unroll
                for (int i = 0; i < 8; i++) {
                    float4 p = *(const float4*)&Ps[(wid*8 + i)*64 + k4*4];  // broadcast
                    o_acc[i][0] += p.x*vv[0].x + p.y*vv[1].x + p.z*vv[2].x + p.w*vv[3].x;
                    o_acc[i][1] += p.x*vv[0].y + p.y*vv[1].y + p.z*vv[2].y + p.w*vv[3].y;
                    o_acc[i][2] += p.x*vv[0].z + p.y*vv[1].z + p.z*vv[2].z + p.w*vv[3].z;
                    o_acc[i][3] += p.x*vv[0].w + p.y*vv[1].w + p.z*vv[2].w + p.w*vv[3].w;
                }
            }
            __syncthreads();    // all warps done with Ks/Vs before next tile load
        }

        #pragma unroll
        for (int i = 0; i < 8; i++) {
            float lv = __shfl_sync(0xffffffffu, l_st[i & 3], (i >> 2) << 4);
            float inv = 1.f / lv;
            int r = wid * 8 + i;
            float4 o = make_float4(o_acc[i][0]*inv, o_acc[i][1]*inv,
                                   o_acc[i][2]*inv, o_acc[i][3]*inv);
            *(float4*)&out[((size_t)b*Tn + q0 + r)*HD + lane*4] = o;
        }
    }
}

// ---------------------------------------------------------------------------
extern "C" void kernel_launch(void* const* d_in, const int* in_sizes, int n_in,
                              void* d_out, int out_size)
{
    const float* x  = (const float*)d_in[0];
    const float* Wq = (const float*)d_in[1];
    const float* Wk = (const float*)d_in[2];
    const float* Wv = (const float*)d_in[3];
    const float* cs = (const float*)d_in[4];
    const float* sn = (const float*)d_in[5];
    float* out = (float*)d_out;

    cudaFuncSetAttribute(gemm_kernel,
                         cudaFuncAttributeMaxDynamicSharedMemorySize, GEMM_SMEM);
    cudaFuncSetAttribute(flash_kernel,
                         cudaFuncAttributeMaxDynamicSharedMemorySize, FLASH_SMEM);

    zero_ctr_kernel<<<1, 1>>>();

    const int nx4 = Mn * Cn / 4;          // 8388608
    const int nw4 = HD * Cn / 4;          // 65536
    split_kernel<<<(nx4 + 255)/256, 256>>>(x,  0, 0,                   nx4);
    split_kernel<<<(nw4 + 255)/256, 256>>>(Wq, 1, 0,                   nw4);
    split_kernel<<<(nw4 + 255)/256, 256>>>(Wk, 1, (size_t)HD*Cn,       nw4);
    split_kernel<<<(nw4 + 255)/256, 256>>>(Wv, 1, (size_t)2*HD*Cn,     nw4);

    gemm_kernel<<<dim3(3, Mn/128), 256, GEMM_SMEM>>>(cs, sn);
    flash_kernel<<<296, 256, FLASH_SMEM>>>(out);
}

// round 9
// speedup vs baseline: 3.2372x; 2.1119x over previous
#include <cuda_runtime.h>
#include <cuda_bf16.h>
#include <math.h>
#include <stdint.h>

#define Bn 4
#define Tn 4096
#define Cn 2048
#define HD 128
#define Mn (Bn*Tn)
#define SCALE 0.022097086912079608f   // 1/sqrt(2048)

// ---------------- device scratch (static, no runtime alloc) ----------------
__device__ __nv_bfloat16 g_xh[(size_t)Mn*Cn];
__device__ __nv_bfloat16 g_xl[(size_t)Mn*Cn];
__device__ __nv_bfloat16 g_wh[3*HD*Cn];
__device__ __nv_bfloat16 g_wl[3*HD*Cn];
__device__ __nv_bfloat16 g_Qh[(size_t)Mn*HD], g_Ql[(size_t)Mn*HD];
__device__ __nv_bfloat16 g_Kh[(size_t)Mn*HD], g_Kl[(size_t)Mn*HD];
__device__ __nv_bfloat16 g_Vh[(size_t)Mn*HD], g_Vl[(size_t)Mn*HD];
__device__ int g_ctr;

// ---------------- base-ISA PTX helpers ---------------
__device__ __forceinline__ unsigned smem_u32(const void* p) {
    unsigned a;
    asm("{ .reg .u64 t; cvta.to.shared.u64 t, %1; cvt.u32.u64 %0, t; }" : "=r"(a) : "l"(p));
    return a;
}
#define CP16(dst, src) \
    asm volatile("cp.async.cg.shared.global [%0], [%1], 16;" \
                 :: "r"(dst), "l"(__cvta_generic_to_global((const void*)(src))) : "memory")
#define CP_COMMIT()  asm volatile("cp.async.commit_group;" ::: "memory")
#define CP_WAIT2()   asm volatile("cp.async.wait_group 2;" ::: "memory")
#define CP_WAIT1()   asm volatile("cp.async.wait_group 1;" ::: "memory")
#define CP_WAIT0()   asm volatile("cp.async.wait_group 0;" ::: "memory")

__device__ __forceinline__ void ldsm4(unsigned& r0, unsigned& r1, unsigned& r2, unsigned& r3,
                                      unsigned addr) {
    asm volatile("ldmatrix.sync.aligned.m8n8.x4.shared.b16 {%0,%1,%2,%3}, [%4];"
                 : "=r"(r0), "=r"(r1), "=r"(r2), "=r"(r3) : "r"(addr));
}
__device__ __forceinline__ void ldsm4t(unsigned& r0, unsigned& r1, unsigned& r2, unsigned& r3,
                                       unsigned addr) {
    asm volatile("ldmatrix.sync.aligned.m8n8.x4.trans.shared.b16 {%0,%1,%2,%3}, [%4];"
                 : "=r"(r0), "=r"(r1), "=r"(r2), "=r"(r3) : "r"(addr));
}
__device__ __forceinline__ void mma16816(float* c, const unsigned* a, unsigned b0, unsigned b1) {
    asm volatile(
        "mma.sync.aligned.m16n8k16.row.col.f32.bf16.bf16.f32 "
        "{%0,%1,%2,%3},{%4,%5,%6,%7},{%8,%9},{%0,%1,%2,%3};"
        : "+f"(c[0]), "+f"(c[1]), "+f"(c[2]), "+f"(c[3])
        : "r"(a[0]), "r"(a[1]), "r"(a[2]), "r"(a[3]), "r"(b0), "r"(b1));
}
__device__ __forceinline__ unsigned packbf(float a, float b) {
    __nv_bfloat162 h = __floats2bfloat162_rn(a, b);
    return *(unsigned*)&h;
}

// ---------------------------------------------------------------------------
// split fp32 -> bf16 hi + bf16 lo
// ---------------------------------------------------------------------------
__global__ void split_kernel(const float* __restrict__ src, int sel, size_t off, int n4)
{
    int i = blockIdx.x * blockDim.x + threadIdx.x;
    if (i >= n4) return;
    __nv_bfloat16* hi = (sel == 0 ? g_xh : g_wh) + off;
    __nv_bfloat16* lo = (sel == 0 ? g_xl : g_wl) + off;
    float4 v = ((const float4*)src)[i];
    __nv_bfloat16 h0 = __float2bfloat16(v.x), h1 = __float2bfloat16(v.y);
    __nv_bfloat16 h2 = __float2bfloat16(v.z), h3 = __float2bfloat16(v.w);
    __nv_bfloat16 l0 = __float2bfloat16(v.x - __bfloat162float(h0));
    __nv_bfloat16 l1 = __float2bfloat16(v.y - __bfloat162float(h1));
    __nv_bfloat16 l2 = __float2bfloat16(v.z - __bfloat162float(h2));
    __nv_bfloat16 l3 = __float2bfloat16(v.w - __bfloat162float(h3));
    ((__nv_bfloat162*)hi)[i*2]   = __halves2bfloat162(h0, h1);
    ((__nv_bfloat162*)hi)[i*2+1] = __halves2bfloat162(h2, h3);
    ((__nv_bfloat162*)lo)[i*2]   = __halves2bfloat162(l0, l1);
    ((__nv_bfloat162*)lo)[i*2+1] = __halves2bfloat162(l2, l3);
}

__global__ void zero_ctr_kernel() { g_ctr = 0; }

// ---------------------------------------------------------------------------
// mma.sync projection GEMM (3-stage cp.async pipeline)
// grid (3, 128), 256 threads; epilogue: RoPE (+scale on Q), bf16 hi/lo stores
// ---------------------------------------------------------------------------
#define TILE_B   8192
#define STAGE_B  (4*TILE_B)      // 32KB
#define GEMM_SMEM (3*STAGE_B)    // 96KB

__device__ __forceinline__ unsigned ldsm_addr(unsigned tile_base, int row0, int kg0, int lane) {
    int r  = row0 + (lane & 7) + ((lane >> 3) & 1) * 8;
    int kg = kg0 + (lane >> 4);
    return tile_base + r * 64 + (((unsigned)(kg ^ ((r >> 1) & 3))) << 4);
}

__device__ __forceinline__ void store_hl(__nv_bfloat16* Oh, __nv_bfloat16* Ol,
                                         int m, int col, float a, float b) {
    __nv_bfloat16 ha = __float2bfloat16(a), hb = __float2bfloat16(b);
    __nv_bfloat16 la = __float2bfloat16(a - __bfloat162float(ha));
    __nv_bfloat16 lb = __float2bfloat16(b - __bfloat162float(hb));
    *(__nv_bfloat162*)&Oh[(size_t)m * HD + col] = __halves2bfloat162(ha, hb);
    *(__nv_bfloat162*)&Ol[(size_t)m * HD + col] = __halves2bfloat162(la, lb);
}

__global__ __launch_bounds__(256, 1) void gemm_kernel(const float* __restrict__ cs,
                                                      const float* __restrict__ sn)
{
    extern __shared__ char gsm[];
    const int tid  = threadIdx.x;
    const int wid  = tid >> 5;
    const int lane = tid & 31;
    const int z    = blockIdx.x;
    const int m0   = blockIdx.y * 128;
    const unsigned sbase = smem_u32(gsm);

    const __nv_bfloat16* Ah = g_xh + (size_t)m0 * Cn;
    const __nv_bfloat16* Al = g_xl + (size_t)m0 * Cn;
    const __nv_bfloat16* Bh = g_wh + (size_t)z * HD * Cn;
    const __nv_bfloat16* Bl = g_wl + (size_t)z * HD * Cn;

    const int lrow = tid >> 2;
    const int lg   = tid & 3;

    #define LOAD_CHUNK(cc, soff)                                                  \
    {                                                                             \
        int k0 = (cc) * 32;                                                       \
        _Pragma("unroll")                                                         \
        for (int q = 0; q < 2; q++) {                                             \
            int row = lrow + q * 64;                                              \
            unsigned d = (soff) + row * 64 + (((unsigned)(lg ^ ((row>>1)&3)))<<4);\
            size_t so = (size_t)row * Cn + k0 + lg * 8;                           \
            CP16(sbase + d + 0*TILE_B, Ah + so);                                  \
            CP16(sbase + d + 1*TILE_B, Al + so);                                  \
            CP16(sbase + d + 2*TILE_B, Bh + so);                                  \
            CP16(sbase + d + 3*TILE_B, Bl + so);                                  \
        }                                                                         \
        CP_COMMIT();                                                              \
    }

    const int wm = wid & 3;
    const int wn = wid >> 2;
    const int mrow0 = wm * 32;
    const int nrow0 = wn * 64;

    float c[2][8][4];
    #pragma unroll
    for (int a = 0; a < 2; a++)
        #pragma unroll
        for (int b = 0; b < 8; b++)
            #pragma unroll
            for (int d = 0; d < 4; d++) c[a][b][d] = 0.f;

    LOAD_CHUNK(0, 0u);
    LOAD_CHUNK(1, (unsigned)STAGE_B);

    for (int ch = 0; ch < 64; ch++) {
        const unsigned st = (unsigned)((ch % 3) * STAGE_B);
        if (ch + 2 < 64) { LOAD_CHUNK(ch + 2, (unsigned)(((ch + 2) % 3) * STAGE_B)); CP_WAIT2(); }
        else if (ch + 1 < 64) { CP_WAIT1(); }
        else { CP_WAIT0(); }
        __syncthreads();

        #pragma unroll
        for (int ks = 0; ks < 2; ks++) {
            const int kg0 = ks * 2;
            unsigned ah[2][4], al[2][4], bh[4][4], bl[4][4];
            #pragma unroll
            for (int mt = 0; mt < 2; mt++) {
                unsigned aA = ldsm_addr(sbase + st + 0*TILE_B, mrow0 + mt*16, kg0, lane);
                unsigned aL = ldsm_addr(sbase + st + 1*TILE_B, mrow0 + mt*16, kg0, lane);
                ldsm4(ah[mt][0], ah[mt][1], ah[mt][2], ah[mt][3], aA);
                ldsm4(al[mt][0], al[mt][1], al[mt][2], al[mt][3], aL);
            }
            #pragma unroll
            for (int np = 0; np < 4; np++) {
                unsigned aB = ldsm_addr(sbase + st + 2*TILE_B, nrow0 + np*16, kg0, lane);
                unsigned aC = ldsm_addr(sbase + st + 3*TILE_B, nrow0 + np*16, kg0, lane);
                ldsm4(bh[np][0], bh[np][1], bh[np][2], bh[np][3], aB);
                ldsm4(bl[np][0], bl[np][1], bl[np][2], bl[np][3], aC);
            }
            #pragma unroll
            for (int mt = 0; mt < 2; mt++)
                #pragma unroll
                for (int np = 0; np < 4; np++) {
                    mma16816(c[mt][np*2],   ah[mt], bh[np][0], bh[np][2]);
                    mma16816(c[mt][np*2],   ah[mt], bl[np][0], bl[np][2]);
                    mma16816(c[mt][np*2],   al[mt], bh[np][0], bh[np][2]);
                    mma16816(c[mt][np*2+1], ah[mt], bh[np][1], bh[np][3]);
                    mma16816(c[mt][np*2+1], ah[mt], bl[np][1], bl[np][3]);
                    mma16816(c[mt][np*2+1], al[mt], bh[np][1], bh[np][3]);
                }
        }
        __syncthreads();
    }

    // epilogue: RoPE on Q/K (+ scale on Q); write bf16 hi/lo
    __nv_bfloat16* Oh = (z == 0) ? g_Qh : (z == 1 ? g_Kh : g_Vh);
    __nv_bfloat16* Ol = (z == 0) ? g_Ql : (z == 1 ? g_Kl : g_Vl);
    const int g  = lane >> 2;
    const int t2 = lane & 3;
    #pragma unroll
    for (int mt = 0; mt < 2; mt++) {
        int mA = m0 + mrow0 + mt * 16 + g;
        int tA = mA & (Tn - 1);
        #pragma unroll
        for (int nt = 0; nt < 8; nt++) {
            int col = nrow0 + nt * 8 + t2 * 2;
            float v0 = c[mt][nt][0], v1 = c[mt][nt][1];
            float v2 = c[mt][nt][2], v3 = c[mt][nt][3];
            if (z < 2) {
                int j = col >> 1;
                float c0 = cs[tA*64 + j],     s0 = sn[tA*64 + j];
                float c1 = cs[(tA+8)*64 + j], s1 = sn[(tA+8)*64 + j];
                float r0 = v0*c0 - v1*s0, i0 = v0*s0 + v1*c0;
                float r1 = v2*c1 - v3*s1, i1 = v2*s1 + v3*c1;
                if (z == 0) { r0 *= SCALE; i0 *= SCALE; r1 *= SCALE; i1 *= SCALE; }
                v0 = r0; v1 = i0; v2 = r1; v3 = i1;
            }
            store_hl(Oh, Ol, mA,     col, v0, v1);
            store_hl(Oh, Ol, mA + 8, col, v2, v3);
        }
    }
}

// ---------------------------------------------------------------------------
// Tensor-core flash attention: 64q x 64k tiles, 128 threads (4 warps x m16),
// S and P.V via 3-product bf16 mma.sync; softmax on fragments.
// smem 96KB (Qh|Ql|Kh|Kl|Vh|Vl, 256B rows, XOR swizzle) -> 2 CTAs/SM.
// ---------------------------------------------------------------------------
#define FQH 0
#define FQL 16384
#define FKH 32768
#define FKL 49152
#define FVH 65536
#define FVL 81920
#define FLASH_SMEM 98304
#define NTASKS (Bn * (Tn/64))    // 256

// ldsm address in 256B-row tiles, swizzle: granule g ^= (row & 7)
__device__ __forceinline__ unsigned faddr(unsigned base, int row0, int g0, int lane) {
    int r = row0 + (lane & 7) + ((lane >> 3) & 1) * 8;
    int g = g0 + (lane >> 4);
    return base + r * 256 + (((unsigned)(g ^ (r & 7))) << 4);
}

__global__ __launch_bounds__(128, 2) void flash_kernel(float* __restrict__ out)
{
    extern __shared__ char fsm[];
    __shared__ int t_sh;
    const unsigned sb = smem_u32(fsm);
    const int tid  = threadIdx.x;
    const int wid  = tid >> 5;
    const int lane = tid & 31;
    const int g    = lane >> 2;
    const int t2   = lane & 3;

    while (true) {
        if (tid == 0) t_sh = atomicAdd(&g_ctr, 1);
        __syncthreads();
        const int task = t_sh;
        if (task >= NTASKS) break;
        const int b  = task & 3;
        const int qt = 63 - (task >> 2);      // heavy-first (LPT)
        const int q0 = qt * 64;

        // load Q tile (resident) + KV tile 0
        #pragma unroll
        for (int q = 0; q < 8; q++) {
            int u = tid + q * 128;
            int r = u >> 4, gg = u & 15;
            unsigned d = r * 256 + (((unsigned)(gg ^ (r & 7))) << 4);
            size_t qo = ((size_t)(b*Tn + q0 + r)) * HD + gg * 8;
            size_t ko = ((size_t)(b*Tn + r)) * HD + gg * 8;
            CP16(sb + FQH + d, g_Qh + qo);
            CP16(sb + FQL + d, g_Ql + qo);
            CP16(sb + FKH + d, g_Kh + ko);
            CP16(sb + FKL + d, g_Kl + ko);
            CP16(sb + FVH + d, g_Vh + ko);
            CP16(sb + FVL + d, g_Vl + ko);
        }
        CP_COMMIT(); CP_WAIT0();

        float o[16][4];
        #pragma unroll
        for (int i = 0; i < 16; i++)
            #pragma unroll
            for (int j = 0; j < 4; j++) o[i][j] = 0.f;
        float m_st[2] = {-1e30f, -1e30f};
        float l_st[2] = {0.f, 0.f};

        for (int kt = 0; kt <= qt; kt++) {
            if (kt > 0) {
                __syncthreads();          // prior tile's compute done with K/V
                const int k0 = kt * 64;
                #pragma unroll
                for (int q = 0; q < 8; q++) {
                    int u = tid + q * 128;
                    int r = u >> 4, gg = u & 15;
                    unsigned d = r * 256 + (((unsigned)(gg ^ (r & 7))) << 4);
                    size_t ko = ((size_t)(b*Tn + k0 + r)) * HD + gg * 8;
                    CP16(sb + FKH + d, g_Kh + ko);
                    CP16(sb + FKL + d, g_Kl + ko);
                    CP16(sb + FVH + d, g_Vh + ko);
                    CP16(sb + FVL + d, g_Vl + ko);
                }
                CP_COMMIT(); CP_WAIT0();
            }
            __syncthreads();

            // ---- S = Q K^T (3-product bf16 split; Q carries 1/sqrt(C)) ----
            float c[8][4];
            #pragma unroll
            for (int i = 0; i < 8; i++)
                #pragma unroll
                for (int j = 0; j < 4; j++) c[i][j] = 0.f;

            #pragma unroll
            for (int kc = 0; kc < 8; kc++) {
                unsigned qh[4], ql[4];
                ldsm4(qh[0], qh[1], qh[2], qh[3], faddr(sb + FQH, 16*wid, 2*kc, lane));
                ldsm4(ql[0], ql[1], ql[2], ql[3], faddr(sb + FQL, 16*wid, 2*kc, lane));
                #pragma unroll
                for (int nb = 0; nb < 4; nb++) {
                    unsigned kh[4], kl[4];
                    ldsm4(kh[0], kh[1], kh[2], kh[3], faddr(sb + FKH, 16*nb, 2*kc, lane));
                    ldsm4(kl[0], kl[1], kl[2], kl[3], faddr(sb + FKL, 16*nb, 2*kc, lane));
                    mma16816(c[2*nb],   qh, kh[0], kh[2]);
                    mma16816(c[2*nb],   qh, kl[0], kl[2]);
                    mma16816(c[2*nb],   ql, kh[0], kh[2]);
                    mma16816(c[2*nb+1], qh, kh[1], kh[3]);
                    mma16816(c[2*nb+1], qh, kl[1], kl[3]);
                    mma16816(c[2*nb+1], ql, kh[1], kh[3]);
                }
            }

            // ---- causal mask (diagonal tile only) ----
            if (kt == qt) {
                const int r0 = 16*wid + g, r1 = r0 + 8;
                #pragma unroll
                for (int nt = 0; nt < 8; nt++) {
                    int cb = 8*nt + 2*t2;
                    if (cb     > r0) c[nt][0] = -1e30f;
                    if (cb + 1 > r0) c[nt][1] = -1e30f;
                    if (cb     > r1) c[nt][2] = -1e30f;
                    if (cb + 1 > r1) c[nt][3] = -1e30f;
                }
            }

            // ---- online softmax on fragments (quad shfl over t2 lanes) ----
            float corr[2];
            #pragma unroll
            for (int h = 0; h < 2; h++) {
                float mx = -1e30f;
                #pragma unroll
                for (int nt = 0; nt < 8; nt++)
                    mx = fmaxf(mx, fmaxf(c[nt][2*h], c[nt][2*h+1]));
                mx = fmaxf(mx, __shfl_xor_sync(0xffffffffu, mx, 1));
                mx = fmaxf(mx, __shfl_xor_sync(0xffffffffu, mx, 2));
                float mn = fmaxf(m_st[h], mx);
                corr[h] = __expf(m_st[h] - mn);
                m_st[h] = mn;
                float sum = 0.f;
                #pragma unroll
                for (int nt = 0; nt < 8; nt++) {
                    float p0 = __expf(c[nt][2*h]   - mn);
                    float p1 = __expf(c[nt][2*h+1] - mn);
                    c[nt][2*h] = p0; c[nt][2*h+1] = p1;
                    sum += p0 + p1;
                }
                sum += __shfl_xor_sync(0xffffffffu, sum, 1);
                sum += __shfl_xor_sync(0xffffffffu, sum, 2);
                l_st[h] = l_st[h] * corr[h] + sum;
            }

            // ---- rescale O ----
            #pragma unroll
            for (int nt = 0; nt < 16; nt++) {
                o[nt][0] *= corr[0]; o[nt][1] *= corr[0];
                o[nt][2] *= corr[1]; o[nt][3] *= corr[1];
            }

            // ---- P -> bf16 hi/lo A-fragments (in registers) ----
            unsigned ph[4][4], pl[4][4];
            #pragma unroll
            for (int k2 = 0; k2 < 4; k2++) {
                #pragma unroll
                for (int j = 0; j < 4; j++) {
                    int nt = 2*k2 + (j >> 1);
                    float p0 = c[nt][(j & 1) * 2];
                    float p1 = c[nt][(j & 1) * 2 + 1];
                    float h0 = __bfloat162float(__float2bfloat16(p0));
                    float h1 = __bfloat162float(__float2bfloat16(p1));
                    ph[k2][j] = packbf(p0, p1);
                    pl[k2][j] = packbf(p0 - h0, p1 - h1);
                }
            }

            // ---- O += P V  (V B-frags via ldmatrix.trans) ----
            #pragma unroll
            for (int np = 0; np < 8; np++) {
                #pragma unroll
                for (int k2 = 0; k2 < 4; k2++) {
                    unsigned vh[4], vl[4];
                    ldsm4t(vh[0], vh[1], vh[2], vh[3], faddr(sb + FVH, 16*k2, 2*np, lane));
                    ldsm4t(vl[0], vl[1], vl[2], vl[3], faddr(sb + FVL, 16*k2, 2*np, lane));
                    mma16816(o[2*np],   ph[k2], vh[0], vh[1]);
                    mma16816(o[2*np],   ph[k2], vl[0], vl[1]);
                    mma16816(o[2*np],   pl[k2], vh[0], vh[1]);
                    mma16816(o[2*np+1], ph[k2], vh[2], vh[3]);
                    mma16816(o[2*np+1], ph[k2], vl[2], vl[3]);
                    mma16816(o[2*np+1], pl[k2], vh[2], vh[3]);
                }
            }
        }

        // ---- normalize & write ----
        {
            float i0 = 1.f / l_st[0], i1 = 1.f / l_st[1];
            int r0 = q0 + 16*wid + g;
            #pragma unroll
            for (int nt = 0; nt < 16; nt++) {
                int col = 8*nt + 2*t2;
                *(float2*)&out[((size_t)b*Tn + r0)     * HD + col] =
                    make_float2(o[nt][0]*i0, o[nt][1]*i0);
                *(float2*)&out[((size_t)b*Tn + r0 + 8) * HD + col] =
                    make_float2(o[nt][2]*i1, o[nt][3]*i1);
            }
        }
        __syncthreads();   // all reads of smem done before next task overwrites
    }
}

// ---------------------------------------------------------------------------
extern "C" void kernel_launch(void* const* d_in, const int* in_sizes, int n_in,
                              void* d_out, int out_size)
{
    const float* x  = (const float*)d_in[0];
    const float* Wq = (const float*)d_in[1];
    const float* Wk = (const float*)d_in[2];
    const float* Wv = (const float*)d_in[3];
    const float* cs = (const float*)d_in[4];
    const float* sn = (const float*)d_in[5];
    float* out = (float*)d_out;

    cudaFuncSetAttribute(gemm_kernel,
                         cudaFuncAttributeMaxDynamicSharedMemorySize, GEMM_SMEM);
    cudaFuncSetAttribute(flash_kernel,
                         cudaFuncAttributeMaxDynamicSharedMemorySize, FLASH_SMEM);

    zero_ctr_kernel<<<1, 1>>>();

    const int nx4 = Mn * Cn / 4;
    const int nw4 = HD * Cn / 4;
    split_kernel<<<(nx4 + 255)/256, 256>>>(x,  0, 0,               nx4);
    split_kernel<<<(nw4 + 255)/256, 256>>>(Wq, 1, 0,               nw4);
    split_kernel<<<(nw4 + 255)/256, 256>>>(Wk, 1, (size_t)HD*Cn,   nw4);
    split_kernel<<<(nw4 + 255)/256, 256>>>(Wv, 1, (size_t)2*HD*Cn, nw4);

    gemm_kernel<<<dim3(3, Mn/128), 256, GEMM_SMEM>>>(cs, sn);
    flash_kernel<<<296, 128, FLASH_SMEM>>>(out);
}

// round 10
// speedup vs baseline: 3.2492x; 1.0037x over previous
#include <cuda_runtime.h>
#include <cuda_bf16.h>
#include <math.h>
#include <stdint.h>

#define Bn 4
#define Tn 4096
#define Cn 2048
#define HD 128
#define Mn (Bn*Tn)
#define SCALE 0.022097086912079608f   // 1/sqrt(2048)

// ---------------- device scratch (static, no runtime alloc) ----------------
__device__ __nv_bfloat16 g_wh[3*HD*Cn];
__device__ __nv_bfloat16 g_wl[3*HD*Cn];
__device__ __nv_bfloat16 g_Qh[(size_t)Mn*HD], g_Ql[(size_t)Mn*HD];
__device__ __nv_bfloat16 g_Kh[(size_t)Mn*HD], g_Kl[(size_t)Mn*HD];
__device__ __nv_bfloat16 g_Vh[(size_t)Mn*HD], g_Vl[(size_t)Mn*HD];
__device__ int g_ctr;

// ---------------- base-ISA PTX helpers ---------------
__device__ __forceinline__ unsigned smem_u32(const void* p) {
    unsigned a;
    asm("{ .reg .u64 t; cvta.to.shared.u64 t, %1; cvt.u32.u64 %0, t; }" : "=r"(a) : "l"(p));
    return a;
}
#define CP16(dst, src) \
    asm volatile("cp.async.cg.shared.global [%0], [%1], 16;" \
                 :: "r"(dst), "l"(__cvta_generic_to_global((const void*)(src))) : "memory")
#define CP_COMMIT()  asm volatile("cp.async.commit_group;" ::: "memory")
#define CP_WAIT2()   asm volatile("cp.async.wait_group 2;" ::: "memory")
#define CP_WAIT1()   asm volatile("cp.async.wait_group 1;" ::: "memory")
#define CP_WAIT0()   asm volatile("cp.async.wait_group 0;" ::: "memory")

__device__ __forceinline__ void ldsm4(unsigned& r0, unsigned& r1, unsigned& r2, unsigned& r3,
                                      unsigned addr) {
    asm volatile("ldmatrix.sync.aligned.m8n8.x4.shared.b16 {%0,%1,%2,%3}, [%4];"
                 : "=r"(r0), "=r"(r1), "=r"(r2), "=r"(r3) : "r"(addr));
}
__device__ __forceinline__ void ldsm4t(unsigned& r0, unsigned& r1, unsigned& r2, unsigned& r3,
                                       unsigned addr) {
    asm volatile("ldmatrix.sync.aligned.m8n8.x4.trans.shared.b16 {%0,%1,%2,%3}, [%4];"
                 : "=r"(r0), "=r"(r1), "=r"(r2), "=r"(r3) : "r"(addr));
}
__device__ __forceinline__ void mma16816(float* c, const unsigned* a, unsigned b0, unsigned b1) {
    asm volatile(
        "mma.sync.aligned.m16n8k16.row.col.f32.bf16.bf16.f32 "
        "{%0,%1,%2,%3},{%4,%5,%6,%7},{%8,%9},{%0,%1,%2,%3};"
        : "+f"(c[0]), "+f"(c[1]), "+f"(c[2]), "+f"(c[3])
        : "r"(a[0]), "r"(a[1]), "r"(a[2]), "r"(a[3]), "r"(b0), "r"(b1));
}
__device__ __forceinline__ unsigned packbf(float a, float b) {
    __nv_bfloat162 h = __floats2bfloat162_rn(a, b);
    return *(unsigned*)&h;
}
// hi = rn(bf16x2(a,b)); lo = rn(bf16x2(a - hi.a, b - hi.b))
__device__ __forceinline__ void packhl(float a, float b, unsigned& h, unsigned& l) {
    __nv_bfloat162 hh = __floats2bfloat162_rn(a, b);
    unsigned hb = *(unsigned*)&hh;
    float fa = __uint_as_float(hb << 16);            // bf16 -> fp32 (low half)
    float fb = __uint_as_float(hb & 0xffff0000u);    // bf16 -> fp32 (high half)
    __nv_bfloat162 ll = __floats2bfloat162_rn(a - fa, b - fb);
    h = hb; l = *(unsigned*)&ll;
}

// ---------------------------------------------------------------------------
// weight split fp32 -> bf16 hi/lo (all three W) + zero task counter
// ---------------------------------------------------------------------------
#define NW4 (HD*Cn/4)          // 65536 float4 per weight

__global__ void wsplit_kernel(const float* __restrict__ Wq, const float* __restrict__ Wk,
                              const float* __restrict__ Wv)
{
    int i = blockIdx.x * blockDim.x + threadIdx.x;
    if (i == 0) g_ctr = 0;
    if (i >= 3 * NW4) return;
    int sel = i >> 16;                 // 0..2
    int j   = i & (NW4 - 1);
    const float* src = (sel == 0) ? Wq : (sel == 1 ? Wk : Wv);
    __nv_bfloat16* hi = g_wh + (size_t)sel * HD * Cn;
    __nv_bfloat16* lo = g_wl + (size_t)sel * HD * Cn;
    float4 v = ((const float4*)src)[j];
    unsigned h0, l0, h1, l1;
    packhl(v.x, v.y, h0, l0);
    packhl(v.z, v.w, h1, l1);
    ((uint2*)hi)[j] = make_uint2(h0, h1);
    ((uint2*)lo)[j] = make_uint2(l0, l1);
}

// ---------------------------------------------------------------------------
// mma.sync projection GEMM, A read as fp32 directly from x (no x split).
// grid (3, 128), 256 threads; 3-stage cp.async pipeline.
// Stage layout: A fp32 128 rows x 160B stride (128B data) | Bh | Bl (64B rows)
// ---------------------------------------------------------------------------
#define A_BYTES  (128*160)       // 20480
#define BH_OFF   A_BYTES
#define BL_OFF   (A_BYTES + 8192)
#define STAGE_B  (A_BYTES + 16384)   // 36864
#define GEMM_SMEM (3*STAGE_B)        // 110592

__device__ __forceinline__ unsigned ldsm_addr(unsigned tile_base, int row0, int kg0, int lane) {
    int r  = row0 + (lane & 7) + ((lane >> 3) & 1) * 8;
    int kg = kg0 + (lane >> 4);
    return tile_base + r * 64 + (((unsigned)(kg ^ ((r >> 1) & 3))) << 4);
}

// Build bf16 hi/lo A-fragments from fp32 smem (row stride 160B).
// Fragment mapping (matches ldmatrix.x4 order used for B):
//   reg0: (g,      2t2 | 2t2+1)   reg1: (g+8,    2t2 | 2t2+1)
//   reg2: (g,    8+2t2 | ...)     reg3: (g+8,  8+2t2 | ...)
__device__ __forceinline__ void lda_frag(unsigned abase, int row0, int ks,
                                         int g, int t2, unsigned* ah, unsigned* al) {
    unsigned a0 = abase + (unsigned)(row0 + g) * 160 + (unsigned)ks * 64 + (unsigned)t2 * 8;
    float2 f01, f23, f45, f67;
    asm volatile("ld.shared.v2.f32 {%0,%1}, [%2];" : "=f"(f01.x), "=f"(f01.y) : "r"(a0));
    asm volatile("ld.shared.v2.f32 {%0,%1}, [%2];" : "=f"(f23.x), "=f"(f23.y) : "r"(a0 + 8*160));
    asm volatile("ld.shared.v2.f32 {%0,%1}, [%2];" : "=f"(f45.x), "=f"(f45.y) : "r"(a0 + 32));
    asm volatile("ld.shared.v2.f32 {%0,%1}, [%2];" : "=f"(f67.x), "=f"(f67.y) : "r"(a0 + 8*160 + 32));
    packhl(f01.x, f01.y, ah[0], al[0]);
    packhl(f23.x, f23.y, ah[1], al[1]);
    packhl(f45.x, f45.y, ah[2], al[2]);
    packhl(f67.x, f67.y, ah[3], al[3]);
}

__device__ __forceinline__ void store_hl(__nv_bfloat16* Oh, __nv_bfloat16* Ol,
                                         int m, int col, float a, float b) {
    unsigned h, l;
    packhl(a, b, h, l);
    *(unsigned*)&Oh[(size_t)m * HD + col] = h;
    *(unsigned*)&Ol[(size_t)m * HD + col] = l;
}

__global__ __launch_bounds__(256, 1) void gemm_kernel(const float* __restrict__ x,
                                                      const float* __restrict__ cs,
                                                      const float* __restrict__ sn)
{
    extern __shared__ char gsm[];
    const int tid  = threadIdx.x;
    const int wid  = tid >> 5;
    const int lane = tid & 31;
    const int g    = lane >> 2;
    const int t2   = lane & 3;
    const int z    = blockIdx.x;
    const int m0   = blockIdx.y * 128;
    const unsigned sbase = smem_u32(gsm);

    const float* xA = x + (size_t)m0 * Cn;
    const __nv_bfloat16* Bh = g_wh + (size_t)z * HD * Cn;
    const __nv_bfloat16* Bl = g_wl + (size_t)z * HD * Cn;

    #define LOAD_CHUNK(cc, soff)                                                  \
    {                                                                             \
        int k0 = (cc) * 32;                                                       \
        _Pragma("unroll")                                                         \
        for (int q = 0; q < 4; q++) {                                             \
            int row = (tid >> 3) + q * 32;                                        \
            unsigned d = (soff) + row * 160 + (tid & 7) * 16;                     \
            CP16(sbase + d, xA + (size_t)row * Cn + k0 + (tid & 7) * 4);          \
        }                                                                         \
        _Pragma("unroll")                                                         \
        for (int q = 0; q < 2; q++) {                                             \
            int row = (tid >> 2) + q * 64;                                        \
            int lg  = tid & 3;                                                    \
            unsigned d = (soff) + row * 64 + (((unsigned)(lg ^ ((row>>1)&3)))<<4);\
            size_t so = (size_t)row * Cn + k0 + lg * 8;                           \
            CP16(sbase + d + BH_OFF, Bh + so);                                    \
            CP16(sbase + d + BL_OFF, Bl + so);                                    \
        }                                                                         \
        CP_COMMIT();                                                              \
    }

    const int wm = wid & 3;
    const int wn = wid >> 2;
    const int mrow0 = wm * 32;
    const int nrow0 = wn * 64;

    float c[2][8][4];
    #pragma unroll
    for (int a = 0; a < 2; a++)
        #pragma unroll
        for (int b = 0; b < 8; b++)
            #pragma unroll
            for (int d = 0; d < 4; d++) c[a][b][d] = 0.f;

    LOAD_CHUNK(0, 0u);
    LOAD_CHUNK(1, (unsigned)STAGE_B);

    for (int ch = 0; ch < 64; ch++) {
        const unsigned st = (unsigned)((ch % 3) * STAGE_B);
        if (ch + 2 < 64) { LOAD_CHUNK(ch + 2, (unsigned)(((ch + 2) % 3) * STAGE_B)); CP_WAIT2(); }
        else if (ch + 1 < 64) { CP_WAIT1(); }
        else { CP_WAIT0(); }
        __syncthreads();

        #pragma unroll
        for (int ks = 0; ks < 2; ks++) {
            const int kg0 = ks * 2;
            unsigned ah[2][4], al[2][4], bh[4][4], bl[4][4];
            #pragma unroll
            for (int mt = 0; mt < 2; mt++)
                lda_frag(sbase + st, mrow0 + mt*16, ks, g, t2, ah[mt], al[mt]);
            #pragma unroll
            for (int np = 0; np < 4; np++) {
                unsigned aB = ldsm_addr(sbase + st + BH_OFF, nrow0 + np*16, kg0, lane);
                unsigned aC = ldsm_addr(sbase + st + BL_OFF, nrow0 + np*16, kg0, lane);
                ldsm4(bh[np][0], bh[np][1], bh[np][2], bh[np][3], aB);
                ldsm4(bl[np][0], bl[np][1], bl[np][2], bl[np][3], aC);
            }
            #pragma unroll
            for (int mt = 0; mt < 2; mt++)
                #pragma unroll
                for (int np = 0; np < 4; np++) {
                    mma16816(c[mt][np*2],   ah[mt], bh[np][0], bh[np][2]);
                    mma16816(c[mt][np*2],   ah[mt], bl[np][0], bl[np][2]);
                    mma16816(c[mt][np*2],   al[mt], bh[np][0], bh[np][2]);
                    mma16816(c[mt][np*2+1], ah[mt], bh[np][1], bh[np][3]);
                    mma16816(c[mt][np*2+1], ah[mt], bl[np][1], bl[np][3]);
                    mma16816(c[mt][np*2+1], al[mt], bh[np][1], bh[np][3]);
                }
        }
        __syncthreads();
    }

    // epilogue: RoPE on Q/K (+ scale on Q); write bf16 hi/lo
    __nv_bfloat16* Oh = (z == 0) ? g_Qh : (z == 1 ? g_Kh : g_Vh);
    __nv_bfloat16* Ol = (z == 0) ? g_Ql : (z == 1 ? g_Kl : g_Vl);
    #pragma unroll
    for (int mt = 0; mt < 2; mt++) {
        int mA = m0 + mrow0 + mt * 16 + g;
        int tA = mA & (Tn - 1);
        #pragma unroll
        for (int nt = 0; nt < 8; nt++) {
            int col = nrow0 + nt * 8 + t2 * 2;
            float v0 = c[mt][nt][0], v1 = c[mt][nt][1];
            float v2 = c[mt][nt][2], v3 = c[mt][nt][3];
            if (z < 2) {
                int j = col >> 1;
                float c0 = cs[tA*64 + j],     s0 = sn[tA*64 + j];
                float c1 = cs[(tA+8)*64 + j], s1 = sn[(tA+8)*64 + j];
                float r0 = v0*c0 - v1*s0, i0 = v0*s0 + v1*c0;
                float r1 = v2*c1 - v3*s1, i1 = v2*s1 + v3*c1;
                if (z == 0) { r0 *= SCALE; i0 *= SCALE; r1 *= SCALE; i1 *= SCALE; }
                v0 = r0; v1 = i0; v2 = r1; v3 = i1;
            }
            store_hl(Oh, Ol, mA,     col, v0, v1);
            store_hl(Oh, Ol, mA + 8, col, v2, v3);
        }
    }
}

// ---------------------------------------------------------------------------
// Tensor-core flash attention: 64q x 64k tiles, 128 threads (4 warps x m16),
// S and P.V via 3-product bf16 mma.sync; softmax on fragments.
// smem 96KB (Qh|Ql|Kh|Kl|Vh|Vl, 256B rows, XOR swizzle) -> 2 CTAs/SM.
// ---------------------------------------------------------------------------
#define FQH 0
#define FQL 16384
#define FKH 32768
#define FKL 49152
#define FVH 65536
#define FVL 81920
#define FLASH_SMEM 98304
#define NTASKS (Bn * (Tn/64))    // 256

// ldsm address in 256B-row tiles, swizzle: granule g ^= (row & 7)
__device__ __forceinline__ unsigned faddr(unsigned base, int row0, int g0, int lane) {
    int r = row0 + (lane & 7) + ((lane >> 3) & 1) * 8;
    int g = g0 + (lane >> 4);
    return base + r * 256 + (((unsigned)(g ^ (r & 7))) << 4);
}

__global__ __launch_bounds__(128, 2) void flash_kernel(float* __restrict__ out)
{
    extern __shared__ char fsm[];
    __shared__ int t_sh;
    const unsigned sb = smem_u32(fsm);
    const int tid  = threadIdx.x;
    const int wid  = tid >> 5;
    const int lane = tid & 31;
    const int g    = lane >> 2;
    const int t2   = lane & 3;

    while (true) {
        if (tid == 0) t_sh = atomicAdd(&g_ctr, 1);
        __syncthreads();
        const int task = t_sh;
        if (task >= NTASKS) break;
        const int b  = task & 3;
        const int qt = 63 - (task >> 2);      // heavy-first (LPT)
        const int q0 = qt * 64;

        // load Q tile (resident) + KV tile 0
        #pragma unroll
        for (int q = 0; q < 8; q++) {
            int u = tid + q * 128;
            int r = u >> 4, gg = u & 15;
            unsigned d = r * 256 + (((unsigned)(gg ^ (r & 7))) << 4);
            size_t qo = ((size_t)(b*Tn + q0 + r)) * HD + gg * 8;
            size_t ko = ((size_t)(b*Tn + r)) * HD + gg * 8;
            CP16(sb + FQH + d, g_Qh + qo);
            CP16(sb + FQL + d, g_Ql + qo);
            CP16(sb + FKH + d, g_Kh + ko);
            CP16(sb + FKL + d, g_Kl + ko);
            CP16(sb + FVH + d, g_Vh + ko);
            CP16(sb + FVL + d, g_Vl + ko);
        }
        CP_COMMIT(); CP_WAIT0();

        float o[16][4];
        #pragma unroll
        for (int i = 0; i < 16; i++)
            #pragma unroll
            for (int j = 0; j < 4; j++) o[i][j] = 0.f;
        float m_st[2] = {-1e30f, -1e30f};
        float l_st[2] = {0.f, 0.f};

        for (int kt = 0; kt <= qt; kt++) {
            if (kt > 0) {
                __syncthreads();          // prior tile's compute done with K/V
                const int k0 = kt * 64;
                #pragma unroll
                for (int q = 0; q < 8; q++) {
                    int u = tid + q * 128;
                    int r = u >> 4, gg = u & 15;
                    unsigned d = r * 256 + (((unsigned)(gg ^ (r & 7))) << 4);
                    size_t ko = ((size_t)(b*Tn + k0 + r)) * HD + gg * 8;
                    CP16(sb + FKH + d, g_Kh + ko);
                    CP16(sb + FKL + d, g_Kl + ko);
                    CP16(sb + FVH + d, g_Vh + ko);
                    CP16(sb + FVL + d, g_Vl + ko);
                }
                CP_COMMIT(); CP_WAIT0();
            }
            __syncthreads();

            // ---- S = Q K^T (3-product bf16 split; Q carries 1/sqrt(C)) ----
            float c[8][4];
            #pragma unroll
            for (int i = 0; i < 8; i++)
                #pragma unroll
                for (int j = 0; j < 4; j++) c[i][j] = 0.f;

            #pragma unroll
            for (int kc = 0; kc < 8; kc++) {
                unsigned qh[4], ql[4];
                ldsm4(qh[0], qh[1], qh[2], qh[3], faddr(sb + FQH, 16*wid, 2*kc, lane));
                ldsm4(ql[0], ql[1], ql[2], ql[3], faddr(sb + FQL, 16*wid, 2*kc, lane));
                #pragma unroll
                for (int nb = 0; nb < 4; nb++) {
                    unsigned kh[4], kl[4];
                    ldsm4(kh[0], kh[1], kh[2], kh[3], faddr(sb + FKH, 16*nb, 2*kc, lane));
                    ldsm4(kl[0], kl[1], kl[2], kl[3], faddr(sb + FKL, 16*nb, 2*kc, lane));
                    mma16816(c[2*nb],   qh, kh[0], kh[2]);
                    mma16816(c[2*nb],   qh, kl[0], kl[2]);
                    mma16816(c[2*nb],   ql, kh[0], kh[2]);
                    mma16816(c[2*nb+1], qh, kh[1], kh[3]);
                    mma16816(c[2*nb+1], qh, kl[1], kl[3]);
                    mma16816(c[2*nb+1], ql, kh[1], kh[3]);
                }
            }

            // ---- causal mask (diagonal tile only) ----
            if (kt == qt) {
                const int r0 = 16*wid + g, r1 = r0 + 8;
                #pragma unroll
                for (int nt = 0; nt < 8; nt++) {
                    int cb = 8*nt + 2*t2;
                    if (cb     > r0) c[nt][0] = -1e30f;
                    if (cb + 1 > r0) c[nt][1] = -1e30f;
                    if (cb     > r1) c[nt][2] = -1e30f;
                    if (cb + 1 > r1) c[nt][3] = -1e30f;
                }
            }

            // ---- online softmax on fragments (quad shfl over t2 lanes) ----
            float corr[2];
            #pragma unroll
            for (int h = 0; h < 2; h++) {
                float mx = -1e30f;
                #pragma unroll
                for (int nt = 0; nt < 8; nt++)
                    mx = fmaxf(mx, fmaxf(c[nt][2*h], c[nt][2*h+1]));
                mx = fmaxf(mx, __shfl_xor_sync(0xffffffffu, mx, 1));
                mx = fmaxf(mx, __shfl_xor_sync(0xffffffffu, mx, 2));
                float mn = fmaxf(m_st[h], mx);
                corr[h] = __expf(m_st[h] - mn);
                m_st[h] = mn;
                float sum = 0.f;
                #pragma unroll
                for (int nt = 0; nt < 8; nt++) {
                    float p0 = __expf(c[nt][2*h]   - mn);
                    float p1 = __expf(c[nt][2*h+1] - mn);
                    c[nt][2*h] = p0; c[nt][2*h+1] = p1;
                    sum += p0 + p1;
                }
                sum += __shfl_xor_sync(0xffffffffu, sum, 1);
                sum += __shfl_xor_sync(0xffffffffu, sum, 2);
                l_st[h] = l_st[h] * corr[h] + sum;
            }

            // ---- rescale O ----
            #pragma unroll
            for (int nt = 0; nt < 16; nt++) {
                o[nt][0] *= corr[0]; o[nt][1] *= corr[0];
                o[nt][2] *= corr[1]; o[nt][3] *= corr[1];
            }

            // ---- P -> bf16 hi/lo A-fragments (in registers) ----
            unsigned ph[4][4], pl[4][4];
            #pragma unroll
            for (int k2 = 0; k2 < 4; k2++) {
                #pragma unroll
                for (int j = 0; j < 4; j++) {
                    int nt = 2*k2 + (j >> 1);
                    float p0 = c[nt][(j & 1) * 2];
                    float p1 = c[nt][(j & 1) * 2 + 1];
                    float h0 = __bfloat162float(__float2bfloat16(p0));
                    float h1 = __bfloat162float(__float2bfloat16(p1));
                    ph[k2][j] = packbf(p0, p1);
                    pl[k2][j] = packbf(p0 - h0, p1 - h1);
                }
            }

            // ---- O += P V  (V B-frags via ldmatrix.trans) ----
            #pragma unroll
            for (int np = 0; np < 8; np++) {
                #pragma unroll
                for (int k2 = 0; k2 < 4; k2++) {
                    unsigned vh[4], vl[4];
                    ldsm4t(vh[0], vh[1], vh[2], vh[3], faddr(sb + FVH, 16*k2, 2*np, lane));
                    ldsm4t(vl[0], vl[1], vl[2], vl[3], faddr(sb + FVL, 16*k2, 2*np, lane));
                    mma16816(o[2*np],   ph[k2], vh[0], vh[1]);
                    mma16816(o[2*np],   ph[k2], vl[0], vl[1]);
                    mma16816(o[2*np],   pl[k2], vh[0], vh[1]);
                    mma16816(o[2*np+1], ph[k2], vh[2], vh[3]);
                    mma16816(o[2*np+1], ph[k2], vl[2], vl[3]);
                    mma16816(o[2*np+1], pl[k2], vh[2], vh[3]);
                }
            }
        }

        // ---- normalize & write ----
        {
            float i0 = 1.f / l_st[0], i1 = 1.f / l_st[1];
            int r0 = q0 + 16*wid + g;
            #pragma unroll
            for (int nt = 0; nt < 16; nt++) {
                int col = 8*nt + 2*t2;
                *(float2*)&out[((size_t)b*Tn + r0)     * HD + col] =
                    make_float2(o[nt][0]*i0, o[nt][1]*i0);
                *(float2*)&out[((size_t)b*Tn + r0 + 8) * HD + col] =
                    make_float2(o[nt][2]*i1, o[nt][3]*i1);
            }
        }
        __syncthreads();   // all reads of smem done before next task overwrites
    }
}

// ---------------------------------------------------------------------------
extern "C" void kernel_launch(void* const* d_in, const int* in_sizes, int n_in,
                              void* d_out, int out_size)
{
    const float* x  = (const float*)d_in[0];
    const float* Wq = (const float*)d_in[1];
    const float* Wk = (const float*)d_in[2];
    const float* Wv = (const float*)d_in[3];
    const float* cs = (const float*)d_in[4];
    const float* sn = (const float*)d_in[5];
    float* out = (float*)d_out;

    cudaFuncSetAttribute(gemm_kernel,
                         cudaFuncAttributeMaxDynamicSharedMemorySize, GEMM_SMEM);
    cudaFuncSetAttribute(flash_kernel,
                         cudaFuncAttributeMaxDynamicSharedMemorySize, FLASH_SMEM);

    wsplit_kernel<<<(3*NW4 + 255)/256, 256>>>(Wq, Wk, Wv);
    gemm_kernel<<<dim3(3, Mn/128), 256, GEMM_SMEM>>>(x, cs, sn);
    flash_kernel<<<296, 128, FLASH_SMEM>>>(out);
}

// round 11
// speedup vs baseline: 3.5601x; 1.0957x over previous
#include <cuda_runtime.h>
#include <cuda_bf16.h>
#include <math.h>
#include <stdint.h>

#define Bn 4
#define Tn 4096
#define Cn 2048
#define HD 128
#define Mn (Bn*Tn)
#define SCALE 0.022097086912079608f   // 1/sqrt(2048)

// ---------------- device scratch (static, no runtime alloc) ----------------
__device__ __nv_bfloat16 g_wh[3*HD*Cn];
__device__ __nv_bfloat16 g_wl[3*HD*Cn];
__device__ __nv_bfloat16 g_Qh[(size_t)Mn*HD];
__device__ __nv_bfloat16 g_Kh[(size_t)Mn*HD], g_Kl[(size_t)Mn*HD];
__device__ __nv_bfloat16 g_Vh[(size_t)Mn*HD], g_Vl[(size_t)Mn*HD];
__device__ int g_ctr;

// ---------------- base-ISA PTX helpers ---------------
__device__ __forceinline__ unsigned smem_u32(const void* p) {
    unsigned a;
    asm("{ .reg .u64 t; cvta.to.shared.u64 t, %1; cvt.u32.u64 %0, t; }" : "=r"(a) : "l"(p));
    return a;
}
#define CP16(dst, src) \
    asm volatile("cp.async.cg.shared.global [%0], [%1], 16;" \
                 :: "r"(dst), "l"(__cvta_generic_to_global((const void*)(src))) : "memory")
#define CP_COMMIT()  asm volatile("cp.async.commit_group;" ::: "memory")
#define CP_WAIT2()   asm volatile("cp.async.wait_group 2;" ::: "memory")
#define CP_WAIT1()   asm volatile("cp.async.wait_group 1;" ::: "memory")
#define CP_WAIT0()   asm volatile("cp.async.wait_group 0;" ::: "memory")

__device__ __forceinline__ void ldsm4(unsigned& r0, unsigned& r1, unsigned& r2, unsigned& r3,
                                      unsigned addr) {
    asm volatile("ldmatrix.sync.aligned.m8n8.x4.shared.b16 {%0,%1,%2,%3}, [%4];"
                 : "=r"(r0), "=r"(r1), "=r"(r2), "=r"(r3) : "r"(addr));
}
__device__ __forceinline__ void ldsm4t(unsigned& r0, unsigned& r1, unsigned& r2, unsigned& r3,
                                       unsigned addr) {
    asm volatile("ldmatrix.sync.aligned.m8n8.x4.trans.shared.b16 {%0,%1,%2,%3}, [%4];"
                 : "=r"(r0), "=r"(r1), "=r"(r2), "=r"(r3) : "r"(addr));
}
__device__ __forceinline__ void mma16816(float* c, const unsigned* a, unsigned b0, unsigned b1) {
    asm volatile(
        "mma.sync.aligned.m16n8k16.row.col.f32.bf16.bf16.f32 "
        "{%0,%1,%2,%3},{%4,%5,%6,%7},{%8,%9},{%0,%1,%2,%3};"
        : "+f"(c[0]), "+f"(c[1]), "+f"(c[2]), "+f"(c[3])
        : "r"(a[0]), "r"(a[1]), "r"(a[2]), "r"(a[3]), "r"(b0), "r"(b1));
}
__device__ __forceinline__ unsigned packbf(float a, float b) {
    __nv_bfloat162 h = __floats2bfloat162_rn(a, b);
    return *(unsigned*)&h;
}
// hi = rn(bf16x2(a,b)); lo = rn(bf16x2(a - hi.a, b - hi.b))
__device__ __forceinline__ void packhl(float a, float b, unsigned& h, unsigned& l) {
    __nv_bfloat162 hh = __floats2bfloat162_rn(a, b);
    unsigned hb = *(unsigned*)&hh;
    float fa = __uint_as_float(hb << 16);
    float fb = __uint_as_float(hb & 0xffff0000u);
    __nv_bfloat162 ll = __floats2bfloat162_rn(a - fa, b - fb);
    h = hb; l = *(unsigned*)&ll;
}

// ---------------------------------------------------------------------------
// weight split fp32 -> bf16 hi/lo (all three W) + zero task counter
// ---------------------------------------------------------------------------
#define NW4 (HD*Cn/4)          // 65536 float4 per weight

__global__ void wsplit_kernel(const float* __restrict__ Wq, const float* __restrict__ Wk,
                              const float* __restrict__ Wv)
{
    int i = blockIdx.x * blockDim.x + threadIdx.x;
    if (i == 0) g_ctr = 0;
    if (i >= 3 * NW4) return;
    int sel = i >> 16;
    int j   = i & (NW4 - 1);
    const float* src = (sel == 0) ? Wq : (sel == 1 ? Wk : Wv);
    __nv_bfloat16* hi = g_wh + (size_t)sel * HD * Cn;
    __nv_bfloat16* lo = g_wl + (size_t)sel * HD * Cn;
    float4 v = ((const float4*)src)[j];
    unsigned h0, l0, h1, l1;
    packhl(v.x, v.y, h0, l0);
    packhl(v.z, v.w, h1, l1);
    ((uint2*)hi)[j] = make_uint2(h0, h1);
    ((uint2*)lo)[j] = make_uint2(l0, l1);
}

// ---------------------------------------------------------------------------
// mma.sync projection GEMM. M-tile 64, N=128, K=2048; 2 CTAs/SM; 3-stage.
// Q,K: 2 products (Ah.Bh + Ah.Bl).  V: 3 products (+ Al.Bh).
// Stage: A fp32 64 rows x 160B | Bh | Bl (64B rows)
// ---------------------------------------------------------------------------
#define A_BYTES  (64*160)            // 10240
#define BH_OFF   A_BYTES
#define BL_OFF   (A_BYTES + 8192)
#define STAGE_B  (A_BYTES + 16384)   // 26624
#define GEMM_SMEM (3*STAGE_B)        // 79872

__device__ __forceinline__ unsigned ldsm_addr(unsigned tile_base, int row0, int kg0, int lane) {
    int r  = row0 + (lane & 7) + ((lane >> 3) & 1) * 8;
    int kg = kg0 + (lane >> 4);
    return tile_base + r * 64 + (((unsigned)(kg ^ ((r >> 1) & 3))) << 4);
}

// bf16 hi/lo A-fragments from fp32 smem (row stride 160B)
__device__ __forceinline__ void lda_frag(unsigned abase, int row0, int ks,
                                         int g, int t2, unsigned* ah, unsigned* al) {
    unsigned a0 = abase + (unsigned)(row0 + g) * 160 + (unsigned)ks * 64 + (unsigned)t2 * 8;
    float2 f01, f23, f45, f67;
    asm volatile("ld.shared.v2.f32 {%0,%1}, [%2];" : "=f"(f01.x), "=f"(f01.y) : "r"(a0));
    asm volatile("ld.shared.v2.f32 {%0,%1}, [%2];" : "=f"(f23.x), "=f"(f23.y) : "r"(a0 + 8*160));
    asm volatile("ld.shared.v2.f32 {%0,%1}, [%2];" : "=f"(f45.x), "=f"(f45.y) : "r"(a0 + 32));
    asm volatile("ld.shared.v2.f32 {%0,%1}, [%2];" : "=f"(f67.x), "=f"(f67.y) : "r"(a0 + 8*160 + 32));
    packhl(f01.x, f01.y, ah[0], al[0]);
    packhl(f23.x, f23.y, ah[1], al[1]);
    packhl(f45.x, f45.y, ah[2], al[2]);
    packhl(f67.x, f67.y, ah[3], al[3]);
}

__device__ __forceinline__ void store_hl(__nv_bfloat16* Oh, __nv_bfloat16* Ol,
                                         int m, int col, float a, float b) {
    unsigned h, l;
    packhl(a, b, h, l);
    *(unsigned*)&Oh[(size_t)m * HD + col] = h;
    *(unsigned*)&Ol[(size_t)m * HD + col] = l;
}

__global__ __launch_bounds__(256, 2) void gemm_kernel(const float* __restrict__ x,
                                                      const float* __restrict__ cs,
                                                      const float* __restrict__ sn)
{
    extern __shared__ char gsm[];
    const int tid  = threadIdx.x;
    const int wid  = tid >> 5;
    const int lane = tid & 31;
    const int g    = lane >> 2;
    const int t2   = lane & 3;
    const int z    = blockIdx.x;
    const int m0   = blockIdx.y * 64;
    const unsigned sbase = smem_u32(gsm);

    const float* xA = x + (size_t)m0 * Cn;
    const __nv_bfloat16* Bh = g_wh + (size_t)z * HD * Cn;
    const __nv_bfloat16* Bl = g_wl + (size_t)z * HD * Cn;

    #define LOAD_CHUNK(cc, soff)                                                  \
    {                                                                             \
        int k0 = (cc) * 32;                                                       \
        _Pragma("unroll")                                                         \
        for (int q = 0; q < 2; q++) {                                             \
            int u = tid + q * 256;                                                \
            int row = u >> 3, gg = u & 7;                                         \
            unsigned d = (soff) + row * 160 + gg * 16;                            \
            CP16(sbase + d, xA + (size_t)row * Cn + k0 + gg * 4);                 \
        }                                                                         \
        _Pragma("unroll")                                                         \
        for (int q = 0; q < 2; q++) {                                             \
            int row = (tid >> 2) + q * 64;                                        \
            int lg  = tid & 3;                                                    \
            unsigned d = (soff) + row * 64 + (((unsigned)(lg ^ ((row>>1)&3)))<<4);\
            size_t so = (size_t)row * Cn + k0 + lg * 8;                           \
            CP16(sbase + d + BH_OFF, Bh + so);                                    \
            CP16(sbase + d + BL_OFF, Bl + so);                                    \
        }                                                                         \
        CP_COMMIT();                                                              \
    }

    const int wm = wid & 3;             // 4 m-groups x 16 rows
    const int wn = wid >> 2;            // 2 n-groups x 64 cols
    const int mrow0 = wm * 16;
    const int nrow0 = wn * 64;

    float c[8][4];
    #pragma unroll
    for (int b = 0; b < 8; b++)
        #pragma unroll
        for (int d = 0; d < 4; d++) c[b][d] = 0.f;

    LOAD_CHUNK(0, 0u);
    LOAD_CHUNK(1, (unsigned)STAGE_B);

    for (int ch = 0; ch < 64; ch++) {
        const unsigned st = (unsigned)((ch % 3) * STAGE_B);
        if (ch + 2 < 64) { LOAD_CHUNK(ch + 2, (unsigned)(((ch + 2) % 3) * STAGE_B)); CP_WAIT2(); }
        else if (ch + 1 < 64) { CP_WAIT1(); }
        else { CP_WAIT0(); }
        __syncthreads();

        #pragma unroll
        for (int ks = 0; ks < 2; ks++) {
            const int kg0 = ks * 2;
            unsigned ah[4], al[4], bh[4][4], bl[4][4];
            lda_frag(sbase + st, mrow0, ks, g, t2, ah, al);
            #pragma unroll
            for (int np = 0; np < 4; np++) {
                unsigned aB = ldsm_addr(sbase + st + BH_OFF, nrow0 + np*16, kg0, lane);
                unsigned aC = ldsm_addr(sbase + st + BL_OFF, nrow0 + np*16, kg0, lane);
                ldsm4(bh[np][0], bh[np][1], bh[np][2], bh[np][3], aB);
                ldsm4(bl[np][0], bl[np][1], bl[np][2], bl[np][3], aC);
            }
            #pragma unroll
            for (int np = 0; np < 4; np++) {
                mma16816(c[np*2],   ah, bh[np][0], bh[np][2]);
                mma16816(c[np*2],   ah, bl[np][0], bl[np][2]);
                mma16816(c[np*2+1], ah, bh[np][1], bh[np][3]);
                mma16816(c[np*2+1], ah, bl[np][1], bl[np][3]);
                if (z == 2) {   // V needs the third product
                    mma16816(c[np*2],   al, bh[np][0], bh[np][2]);
                    mma16816(c[np*2+1], al, bh[np][1], bh[np][3]);
                }
            }
        }
        __syncthreads();
    }

    // epilogue: RoPE on Q/K (+ scale on Q); Q: hi only, K/V: hi+lo
    __nv_bfloat16* Oh = (z == 0) ? g_Qh : (z == 1 ? g_Kh : g_Vh);
    __nv_bfloat16* Ol = (z == 1) ? g_Kl : g_Vl;
    {
        int mA = m0 + mrow0 + g;
        int tA = mA & (Tn - 1);
        #pragma unroll
        for (int nt = 0; nt < 8; nt++) {
            int col = nrow0 + nt * 8 + t2 * 2;
            float v0 = c[nt][0], v1 = c[nt][1];
            float v2 = c[nt][2], v3 = c[nt][3];
            if (z < 2) {
                int j = col >> 1;
                float c0 = cs[tA*64 + j],     s0 = sn[tA*64 + j];
                float c1 = cs[(tA+8)*64 + j], s1 = sn[(tA+8)*64 + j];
                float r0 = v0*c0 - v1*s0, i0 = v0*s0 + v1*c0;
                float r1 = v2*c1 - v3*s1, i1 = v2*s1 + v3*c1;
                if (z == 0) { r0 *= SCALE; i0 *= SCALE; r1 *= SCALE; i1 *= SCALE; }
                v0 = r0; v1 = i0; v2 = r1; v3 = i1;
            }
            if (z == 0) {
                *(unsigned*)&Oh[(size_t)mA * HD + col]       = packbf(v0, v1);
                *(unsigned*)&Oh[(size_t)(mA + 8) * HD + col] = packbf(v2, v3);
            } else {
                store_hl(Oh, Ol, mA,     col, v0, v1);
                store_hl(Oh, Ol, mA + 8, col, v2, v3);
            }
        }
    }
}

// ---------------------------------------------------------------------------
// Tensor-core flash attention. S = Qh.(Kh+Kl) (2 products), P.V 3 products.
// Pipelined K/V commit groups: K(t+1) loads during PV, V(t+1) during next S.
// smem 80KB (Qh|Kh|Kl|Vh|Vl) -> 2 CTAs/SM.
// ---------------------------------------------------------------------------
#define FQH 0
#define FKH 16384
#define FKL 32768
#define FVH 49152
#define FVL 65536
#define FLASH_SMEM 81920
#define NTASKS (Bn * (Tn/64))    // 256

__device__ __forceinline__ unsigned faddr(unsigned base, int row0, int g0, int lane) {
    int r = row0 + (lane & 7) + ((lane >> 3) & 1) * 8;
    int g = g0 + (lane >> 4);
    return base + r * 256 + (((unsigned)(g ^ (r & 7))) << 4);
}

__global__ __launch_bounds__(128, 2) void flash_kernel(float* __restrict__ out)
{
    extern __shared__ char fsm[];
    __shared__ int t_sh;
    const unsigned sb = smem_u32(fsm);
    const int tid  = threadIdx.x;
    const int wid  = tid >> 5;
    const int lane = tid & 31;
    const int g    = lane >> 2;
    const int t2   = lane & 3;

    // loader indices: u = tid + q*128 -> row u>>4 (0..63), granule u&15
    #define LOAD_KV_K(b, k0)                                                    \
    {                                                                           \
        _Pragma("unroll")                                                       \
        for (int q = 0; q < 8; q++) {                                           \
            int u = tid + q * 128;                                              \
            int r = u >> 4, gg = u & 15;                                        \
            unsigned d = r * 256 + (((unsigned)(gg ^ (r & 7))) << 4);           \
            size_t ko = ((size_t)((b)*Tn + (k0) + r)) * HD + gg * 8;            \
            CP16(sb + FKH + d, g_Kh + ko);                                      \
            CP16(sb + FKL + d, g_Kl + ko);                                      \
        }                                                                       \
        CP_COMMIT();                                                            \
    }
    #define LOAD_KV_V(b, k0)                                                    \
    {                                                                           \
        _Pragma("unroll")                                                       \
        for (int q = 0; q < 8; q++) {                                           \
            int u = tid + q * 128;                                              \
            int r = u >> 4, gg = u & 15;                                        \
            unsigned d = r * 256 + (((unsigned)(gg ^ (r & 7))) << 4);           \
            size_t ko = ((size_t)((b)*Tn + (k0) + r)) * HD + gg * 8;            \
            CP16(sb + FVH + d, g_Vh + ko);                                      \
            CP16(sb + FVL + d, g_Vl + ko);                                      \
        }                                                                       \
        CP_COMMIT();                                                            \
    }

    while (true) {
        if (tid == 0) t_sh = atomicAdd(&g_ctr, 1);
        __syncthreads();
        const int task = t_sh;
        if (task >= NTASKS) break;
        const int b  = task & 3;
        const int qt = 63 - (task >> 2);      // heavy-first (LPT)
        const int q0 = qt * 64;

        // group 1: Q + K0 ; group 2: V0
        #pragma unroll
        for (int q = 0; q < 8; q++) {
            int u = tid + q * 128;
            int r = u >> 4, gg = u & 15;
            unsigned d = r * 256 + (((unsigned)(gg ^ (r & 7))) << 4);
            size_t qo = ((size_t)(b*Tn + q0 + r)) * HD + gg * 8;
            size_t ko = ((size_t)(b*Tn + r)) * HD + gg * 8;
            CP16(sb + FQH + d, g_Qh + qo);
            CP16(sb + FKH + d, g_Kh + ko);
            CP16(sb + FKL + d, g_Kl + ko);
        }
        CP_COMMIT();
        LOAD_KV_V(b, 0);

        float o[16][4];
        #pragma unroll
        for (int i = 0; i < 16; i++)
            #pragma unroll
            for (int j = 0; j < 4; j++) o[i][j] = 0.f;
        float m_st[2] = {-1e30f, -1e30f};
        float l_st[2] = {0.f, 0.f};

        for (int kt = 0; kt <= qt; kt++) {
            CP_WAIT1();              // K(kt) (and Q) complete; V(kt) may be in flight
            __syncthreads();

            // ---- S = Qh Kh^T + Qh Kl^T  (Q carries 1/sqrt(C)) ----
            float c[8][4];
            #pragma unroll
            for (int i = 0; i < 8; i++)
                #pragma unroll
                for (int j = 0; j < 4; j++) c[i][j] = 0.f;

            #pragma unroll
            for (int kc = 0; kc < 8; kc++) {
                unsigned qh[4];
                ldsm4(qh[0], qh[1], qh[2], qh[3], faddr(sb + FQH, 16*wid, 2*kc, lane));
                #pragma unroll
                for (int nb = 0; nb < 4; nb++) {
                    unsigned kh[4], kl[4];
                    ldsm4(kh[0], kh[1], kh[2], kh[3], faddr(sb + FKH, 16*nb, 2*kc, lane));
                    ldsm4(kl[0], kl[1], kl[2], kl[3], faddr(sb + FKL, 16*nb, 2*kc, lane));
                    mma16816(c[2*nb],   qh, kh[0], kh[2]);
                    mma16816(c[2*nb],   qh, kl[0], kl[2]);
                    mma16816(c[2*nb+1], qh, kh[1], kh[3]);
                    mma16816(c[2*nb+1], qh, kl[1], kl[3]);
                }
            }

            // ---- causal mask (diagonal tile only) ----
            if (kt == qt) {
                const int r0 = 16*wid + g, r1 = r0 + 8;
                #pragma unroll
                for (int nt = 0; nt < 8; nt++) {
                    int cb = 8*nt + 2*t2;
                    if (cb     > r0) c[nt][0] = -1e30f;
                    if (cb + 1 > r0) c[nt][1] = -1e30f;
                    if (cb     > r1) c[nt][2] = -1e30f;
                    if (cb + 1 > r1) c[nt][3] = -1e30f;
                }
            }

            // ---- online softmax on fragments (quad shfl) ----
            float corr[2];
            #pragma unroll
            for (int h = 0; h < 2; h++) {
                float mx = -1e30f;
                #pragma unroll
                for (int nt = 0; nt < 8; nt++)
                    mx = fmaxf(mx, fmaxf(c[nt][2*h], c[nt][2*h+1]));
                mx = fmaxf(mx, __shfl_xor_sync(0xffffffffu, mx, 1));
                mx = fmaxf(mx, __shfl_xor_sync(0xffffffffu, mx, 2));
                float mn = fmaxf(m_st[h], mx);
                corr[h] = __expf(m_st[h] - mn);
                m_st[h] = mn;
                float sum = 0.f;
                #pragma unroll
                for (int nt = 0; nt < 8; nt++) {
                    float p0 = __expf(c[nt][2*h]   - mn);
                    float p1 = __expf(c[nt][2*h+1] - mn);
                    c[nt][2*h] = p0; c[nt][2*h+1] = p1;
                    sum += p0 + p1;
                }
                sum += __shfl_xor_sync(0xffffffffu, sum, 1);
                sum += __shfl_xor_sync(0xffffffffu, sum, 2);
                l_st[h] = l_st[h] * corr[h] + sum;
            }

            CP_WAIT0();              // V(kt) complete
            __syncthreads();         // all warps past K reads; V visible
            if (kt < qt) LOAD_KV_K(b, (kt + 1) * 64);   // prefetch K during PV

            // ---- rescale O ----
            #pragma unroll
            for (int nt = 0; nt < 16; nt++) {
                o[nt][0] *= corr[0]; o[nt][1] *= corr[0];
                o[nt][2] *= corr[1]; o[nt][3] *= corr[1];
            }

            // ---- P -> bf16 hi/lo A-fragments ----
            unsigned ph[4][4], pl[4][4];
            #pragma unroll
            for (int k2 = 0; k2 < 4; k2++) {
                #pragma unroll
                for (int j = 0; j < 4; j++) {
                    int nt = 2*k2 + (j >> 1);
                    float p0 = c[nt][(j & 1) * 2];
                    float p1 = c[nt][(j & 1) * 2 + 1];
                    float h0 = __bfloat162float(__float2bfloat16(p0));
                    float h1 = __bfloat162float(__float2bfloat16(p1));
                    ph[k2][j] = packbf(p0, p1);
                    pl[k2][j] = packbf(p0 - h0, p1 - h1);
                }
            }

            // ---- O += P V  (3 products) ----
            #pragma unroll
            for (int np = 0; np < 8; np++) {
                #pragma unroll
                for (int k2 = 0; k2 < 4; k2++) {
                    unsigned vh[4], vl[4];
                    ldsm4t(vh[0], vh[1], vh[2], vh[3], faddr(sb + FVH, 16*k2, 2*np, lane));
                    ldsm4t(vl[0], vl[1], vl[2], vl[3], faddr(sb + FVL, 16*k2, 2*np, lane));
                    mma16816(o[2*np],   ph[k2], vh[0], vh[1]);
                    mma16816(o[2*np],   ph[k2], vl[0], vl[1]);
                    mma16816(o[2*np],   pl[k2], vh[0], vh[1]);
                    mma16816(o[2*np+1], ph[k2], vh[2], vh[3]);
                    mma16816(o[2*np+1], ph[k2], vl[2], vl[3]);
                    mma16816(o[2*np+1], pl[k2], vh[2], vh[3]);
                }
            }

            __syncthreads();         // all warps past V reads
            if (kt < qt) LOAD_KV_V(b, (kt + 1) * 64);   // prefetch V during next S
        }

        // ---- normalize & write ----
        {
            float i0 = 1.f / l_st[0], i1 = 1.f / l_st[1];
            int r0 = q0 + 16*wid + g;
            #pragma unroll
            for (int nt = 0; nt < 16; nt++) {
                int col = 8*nt + 2*t2;
                *(float2*)&out[((size_t)b*Tn + r0)     * HD + col] =
                    make_float2(o[nt][0]*i0, o[nt][1]*i0);
                *(float2*)&out[((size_t)b*Tn + r0 + 8) * HD + col] =
                    make_float2(o[nt][2]*i1, o[nt][3]*i1);
            }
        }
    }
}

// ---------------------------------------------------------------------------
extern "C" void kernel_launch(void* const* d_in, const int* in_sizes, int n_in,
                              void* d_out, int out_size)
{
    const float* x  = (const float*)d_in[0];
    const float* Wq = (const float*)d_in[1];
    const float* Wk = (const float*)d_in[2];
    const float* Wv = (const float*)d_in[3];
    const float* cs = (const float*)d_in[4];
    const float* sn = (const float*)d_in[5];
    float* out = (float*)d_out;

    cudaFuncSetAttribute(gemm_kernel,
                         cudaFuncAttributeMaxDynamicSharedMemorySize, GEMM_SMEM);
    cudaFuncSetAttribute(flash_kernel,
                         cudaFuncAttributeMaxDynamicSharedMemorySize, FLASH_SMEM);

    wsplit_kernel<<<(3*NW4 + 255)/256, 256>>>(Wq, Wk, Wv);
    gemm_kernel<<<dim3(3, Mn/64), 256, GEMM_SMEM>>>(x, cs, sn);
    flash_kernel<<<296, 128, FLASH_SMEM>>>(out);
}

// round 12
// speedup vs baseline: 3.7023x; 1.0399x over previous
#include <cuda_runtime.h>
#include <cuda_bf16.h>
#include <math.h>
#include <stdint.h>

#define Bn 4
#define Tn 4096
#define Cn 2048
#define HD 128
#define Mn (Bn*Tn)
#define SCALE 0.022097086912079608f   // 1/sqrt(2048)

// ---------------- device scratch (static, no runtime alloc) ----------------
__device__ float        g_wf[2*(size_t)HD*Cn];        // Wq, Wk (tf32-rounded fp32)
__device__ __nv_bfloat16 g_wh[(size_t)HD*Cn];         // Wv hi
__device__ __nv_bfloat16 g_wl[(size_t)HD*Cn];         // Wv lo
__device__ float        g_Q[(size_t)Mn*HD];           // tf32-rounded fp32
__device__ float        g_K[(size_t)Mn*HD];           // tf32-rounded fp32
__device__ __nv_bfloat16 g_Vh[(size_t)Mn*HD], g_Vl[(size_t)Mn*HD];
__device__ int g_ctr;

// ---------------- base-ISA PTX helpers ---------------
__device__ __forceinline__ unsigned smem_u32(const void* p) {
    unsigned a;
    asm("{ .reg .u64 t; cvta.to.shared.u64 t, %1; cvt.u32.u64 %0, t; }" : "=r"(a) : "l"(p));
    return a;
}
#define CP16(dst, src) \
    asm volatile("cp.async.cg.shared.global [%0], [%1], 16;" \
                 :: "r"(dst), "l"(__cvta_generic_to_global((const void*)(src))) : "memory")
#define CP_COMMIT()  asm volatile("cp.async.commit_group;" ::: "memory")
#define CP_WAIT2()   asm volatile("cp.async.wait_group 2;" ::: "memory")
#define CP_WAIT1()   asm volatile("cp.async.wait_group 1;" ::: "memory")
#define CP_WAIT0()   asm volatile("cp.async.wait_group 0;" ::: "memory")

__device__ __forceinline__ void ldsm4(unsigned& r0, unsigned& r1, unsigned& r2, unsigned& r3,
                                      unsigned addr) {
    asm volatile("ldmatrix.sync.aligned.m8n8.x4.shared.b16 {%0,%1,%2,%3}, [%4];"
                 : "=r"(r0), "=r"(r1), "=r"(r2), "=r"(r3) : "r"(addr));
}
__device__ __forceinline__ void ldsm4t(unsigned& r0, unsigned& r1, unsigned& r2, unsigned& r3,
                                       unsigned addr) {
    asm volatile("ldmatrix.sync.aligned.m8n8.x4.trans.shared.b16 {%0,%1,%2,%3}, [%4];"
                 : "=r"(r0), "=r"(r1), "=r"(r2), "=r"(r3) : "r"(addr));
}
__device__ __forceinline__ void mma16816(float* c, const unsigned* a, unsigned b0, unsigned b1) {
    asm volatile(
        "mma.sync.aligned.m16n8k16.row.col.f32.bf16.bf16.f32 "
        "{%0,%1,%2,%3},{%4,%5,%6,%7},{%8,%9},{%0,%1,%2,%3};"
        : "+f"(c[0]), "+f"(c[1]), "+f"(c[2]), "+f"(c[3])
        : "r"(a[0]), "r"(a[1]), "r"(a[2]), "r"(a[3]), "r"(b0), "r"(b1));
}
__device__ __forceinline__ void mma1688t(float* c, const unsigned* a, unsigned b0, unsigned b1) {
    asm volatile(
        "mma.sync.aligned.m16n8k8.row.col.f32.tf32.tf32.f32 "
        "{%0,%1,%2,%3},{%4,%5,%6,%7},{%8,%9},{%0,%1,%2,%3};"
        : "+f"(c[0]), "+f"(c[1]), "+f"(c[2]), "+f"(c[3])
        : "r"(a[0]), "r"(a[1]), "r"(a[2]), "r"(a[3]), "r"(b0), "r"(b1));
}
__device__ __forceinline__ unsigned cvt_tf32(float f) {
    unsigned r; asm("cvt.rna.tf32.f32 %0, %1;" : "=r"(r) : "f"(f)); return r;
}
__device__ __forceinline__ unsigned packbf(float a, float b) {
    __nv_bfloat162 h = __floats2bfloat162_rn(a, b);
    return *(unsigned*)&h;
}
__device__ __forceinline__ void packhl(float a, float b, unsigned& h, unsigned& l) {
    __nv_bfloat162 hh = __floats2bfloat162_rn(a, b);
    unsigned hb = *(unsigned*)&hh;
    float fa = __uint_as_float(hb << 16);
    float fb = __uint_as_float(hb & 0xffff0000u);
    __nv_bfloat162 ll = __floats2bfloat162_rn(a - fa, b - fb);
    h = hb; l = *(unsigned*)&ll;
}

// ---------------------------------------------------------------------------
// weight prep: Wq,Wk -> tf32 fp32; Wv -> bf16 hi/lo. Also zeros task counter.
// ---------------------------------------------------------------------------
#define NW4 (HD*Cn/4)          // 65536 float4 per weight

__global__ void wsplit_kernel(const float* __restrict__ Wq, const float* __restrict__ Wk,
                              const float* __restrict__ Wv)
{
    int i = blockIdx.x * blockDim.x + threadIdx.x;
    if (i == 0) g_ctr = 0;
    if (i >= 3 * NW4) return;
    int sel = i >> 16;
    int j   = i & (NW4 - 1);
    if (sel < 2) {
        const float* src = (sel == 0) ? Wq : Wk;
        float4 v = ((const float4*)src)[j];
        float4 o;
        o.x = __uint_as_float(cvt_tf32(v.x));
        o.y = __uint_as_float(cvt_tf32(v.y));
        o.z = __uint_as_float(cvt_tf32(v.z));
        o.w = __uint_as_float(cvt_tf32(v.w));
        ((float4*)(g_wf + (size_t)sel * HD * Cn))[j] = o;
    } else {
        float4 v = ((const float4*)Wv)[j];
        unsigned h0, l0, h1, l1;
        packhl(v.x, v.y, h0, l0);
        packhl(v.z, v.w, h1, l1);
        ((uint2*)g_wh)[j] = make_uint2(h0, h1);
        ((uint2*)g_wl)[j] = make_uint2(l0, l1);
    }
}

// ---------------------------------------------------------------------------
// Q/K projection GEMM, single-product tf32. M-tile 64, N=128, K=2048.
// grid (2, 256); 2 CTAs/SM; 3-stage cp.async pipeline.
// Stage: x fp32 64 rows x 144B | W fp32 128 rows x 144B  (bank = 4g+t2, CF)
// ---------------------------------------------------------------------------
#define QK_A_B   (64*144)                // 9216
#define QK_W_OFF QK_A_B
#define QK_STAGE (QK_A_B + 128*144)      // 27648
#define QK_SMEM  (3*QK_STAGE)            // 82944

__global__ __launch_bounds__(256, 2) void gemm_qk_kernel(const float* __restrict__ x,
                                                         const float* __restrict__ cs,
                                                         const float* __restrict__ sn)
{
    extern __shared__ char gsm[];
    const int tid  = threadIdx.x;
    const int wid  = tid >> 5;
    const int lane = tid & 31;
    const int g    = lane >> 2;
    const int t2   = lane & 3;
    const int z    = blockIdx.x;                 // 0=Q, 1=K
    const int m0   = blockIdx.y * 64;
    const unsigned sbase = smem_u32(gsm);

    const float* xA = x + (size_t)m0 * Cn;
    const float* Wf = g_wf + (size_t)z * HD * Cn;

    #define QK_LOAD(cc, soff)                                                 \
    {                                                                         \
        int k0 = (cc) * 32;                                                   \
        _Pragma("unroll")                                                     \
        for (int q = 0; q < 2; q++) {                                         \
            int u = tid + q * 256;                                            \
            int row = u >> 3, gg = u & 7;                                     \
            CP16((soff) + sbase + row * 144 + gg * 16,                        \
                 xA + (size_t)row * Cn + k0 + gg * 4);                        \
        }                                                                     \
        _Pragma("unroll")                                                     \
        for (int q = 0; q < 4; q++) {                                         \
            int u = tid + q * 256;                                            \
            int row = u >> 3, gg = u & 7;                                     \
            CP16((soff) + sbase + QK_W_OFF + row * 144 + gg * 16,             \
                 Wf + (size_t)row * Cn + k0 + gg * 4);                        \
        }                                                                     \
        CP_COMMIT();                                                          \
    }

    const int wm = wid & 3;              // 4 m-groups x 16 rows
    const int wn = wid >> 2;             // 2 n-groups x 64 cols
    const int mrow0 = wm * 16;
    const int nrow0 = wn * 64;

    float c[8][4];
    #pragma unroll
    for (int b = 0; b < 8; b++)
        #pragma unroll
        for (int d = 0; d < 4; d++) c[b][d] = 0.f;

    QK_LOAD(0, 0u);
    QK_LOAD(1, (unsigned)QK_STAGE);

    for (int ch = 0; ch < 64; ch++) {
        const unsigned st = (unsigned)((ch % 3) * QK_STAGE);
        if (ch + 2 < 64) { QK_LOAD(ch + 2, (unsigned)(((ch + 2) % 3) * QK_STAGE)); CP_WAIT2(); }
        else if (ch + 1 < 64) { CP_WAIT1(); }
        else { CP_WAIT0(); }
        __syncthreads();

        #pragma unroll
        for (int k8 = 0; k8 < 4; k8++) {
            // A fragment (x, cvt to tf32 in-register)
            unsigned a[4];
            {
                unsigned ab = sbase + st + (unsigned)(mrow0 + g) * 144
                            + (unsigned)k8 * 32 + (unsigned)t2 * 4;
                float f0, f1, f2, f3;
                asm volatile("ld.shared.f32 %0, [%1];" : "=f"(f0) : "r"(ab));
                asm volatile("ld.shared.f32 %0, [%1];" : "=f"(f1) : "r"(ab + 8*144));
                asm volatile("ld.shared.f32 %0, [%1];" : "=f"(f2) : "r"(ab + 16));
                asm volatile("ld.shared.f32 %0, [%1];" : "=f"(f3) : "r"(ab + 8*144 + 16));
                a[0] = cvt_tf32(f0); a[1] = cvt_tf32(f1);
                a[2] = cvt_tf32(f2); a[3] = cvt_tf32(f3);
            }
            #pragma unroll
            for (int np = 0; np < 8; np++) {
                unsigned bb = sbase + st + QK_W_OFF
                            + (unsigned)(nrow0 + np * 8 + g) * 144
                            + (unsigned)k8 * 32 + (unsigned)t2 * 4;
                unsigned b0, b1;
                asm volatile("ld.shared.b32 %0, [%1];" : "=r"(b0) : "r"(bb));
                asm volatile("ld.shared.b32 %0, [%1];" : "=r"(b1) : "r"(bb + 16));
                mma1688t(c[np], a, b0, b1);
            }
        }
        __syncthreads();
    }

    // epilogue: RoPE (+ scale on Q); store tf32-rounded fp32
    float* Out = (z == 0) ? g_Q : g_K;
    {
        int mA = m0 + mrow0 + g;
        int tA = mA & (Tn - 1);
        #pragma unroll
        for (int np = 0; np < 8; np++) {
            int col = nrow0 + np * 8 + t2 * 2;
            int j = col >> 1;
            float c0 = cs[tA*64 + j],     s0 = sn[tA*64 + j];
            float c1 = cs[(tA+8)*64 + j], s1 = sn[(tA+8)*64 + j];
            float r0 = c[np][0]*c0 - c[np][1]*s0, i0 = c[np][0]*s0 + c[np][1]*c0;
            float r1 = c[np][2]*c1 - c[np][3]*s1, i1 = c[np][2]*s1 + c[np][3]*c1;
            if (z == 0) { r0 *= SCALE; i0 *= SCALE; r1 *= SCALE; i1 *= SCALE; }
            float2 o0 = make_float2(__uint_as_float(cvt_tf32(r0)), __uint_as_float(cvt_tf32(i0)));
            float2 o1 = make_float2(__uint_as_float(cvt_tf32(r1)), __uint_as_float(cvt_tf32(i1)));
            *(float2*)&Out[(size_t)mA * HD + col]       = o0;
            *(float2*)&Out[(size_t)(mA + 8) * HD + col] = o1;
        }
    }
}

// ---------------------------------------------------------------------------
// V projection GEMM: bf16 3-product (unchanged scheme). grid (1, 256).
// ---------------------------------------------------------------------------
#define A_BYTES  (64*160)            // 10240
#define BH_OFF   A_BYTES
#define BL_OFF   (A_BYTES + 8192)
#define STAGE_B  (A_BYTES + 16384)   // 26624
#define V_SMEM   (3*STAGE_B)         // 79872

__device__ __forceinline__ unsigned ldsm_addr(unsigned tile_base, int row0, int kg0, int lane) {
    int r  = row0 + (lane & 7) + ((lane >> 3) & 1) * 8;
    int kg = kg0 + (lane >> 4);
    return tile_base + r * 64 + (((unsigned)(kg ^ ((r >> 1) & 3))) << 4);
}

__device__ __forceinline__ void lda_frag(unsigned abase, int row0, int ks,
                                         int g, int t2, unsigned* ah, unsigned* al) {
    unsigned a0 = abase + (unsigned)(row0 + g) * 160 + (unsigned)ks * 64 + (unsigned)t2 * 8;
    float2 f01, f23, f45, f67;
    asm volatile("ld.shared.v2.f32 {%0,%1}, [%2];" : "=f"(f01.x), "=f"(f01.y) : "r"(a0));
    asm volatile("ld.shared.v2.f32 {%0,%1}, [%2];" : "=f"(f23.x), "=f"(f23.y) : "r"(a0 + 8*160));
    asm volatile("ld.shared.v2.f32 {%0,%1}, [%2];" : "=f"(f45.x), "=f"(f45.y) : "r"(a0 + 32));
    asm volatile("ld.shared.v2.f32 {%0,%1}, [%2];" : "=f"(f67.x), "=f"(f67.y) : "r"(a0 + 8*160 + 32));
    packhl(f01.x, f01.y, ah[0], al[0]);
    packhl(f23.x, f23.y, ah[1], al[1]);
    packhl(f45.x, f45.y, ah[2], al[2]);
    packhl(f67.x, f67.y, ah[3], al[3]);
}

__global__ __launch_bounds__(256, 2) void gemm_v_kernel(const float* __restrict__ x)
{
    extern __shared__ char gsm[];
    const int tid  = threadIdx.x;
    const int wid  = tid >> 5;
    const int lane = tid & 31;
    const int g    = lane >> 2;
    const int t2   = lane & 3;
    const int m0   = blockIdx.y * 64;
    const unsigned sbase = smem_u32(gsm);

    const float* xA = x + (size_t)m0 * Cn;
    const __nv_bfloat16* Bh = g_wh;
    const __nv_bfloat16* Bl = g_wl;

    #define V_LOAD(cc, soff)                                                      \
    {                                                                             \
        int k0 = (cc) * 32;                                                       \
        _Pragma("unroll")                                                         \
        for (int q = 0; q < 2; q++) {                                             \
            int u = tid + q * 256;                                                \
            int row = u >> 3, gg = u & 7;                                         \
            CP16((soff) + sbase + row * 160 + gg * 16,                            \
                 xA + (size_t)row * Cn + k0 + gg * 4);                            \
        }                                                                         \
        _Pragma("unroll")                                                         \
        for (int q = 0; q < 2; q++) {                                             \
            int row = (tid >> 2) + q * 64;                                        \
            int lg  = tid & 3;                                                    \
            unsigned d = (soff) + row * 64 + (((unsigned)(lg ^ ((row>>1)&3)))<<4);\
            size_t so = (size_t)row * Cn + k0 + lg * 8;                           \
            CP16(sbase + d + BH_OFF, Bh + so);                                    \
            CP16(sbase + d + BL_OFF, Bl + so);                                    \
        }                                                                         \
        CP_COMMIT();                                                              \
    }

    const int wm = wid & 3;
    const int wn = wid >> 2;
    const int mrow0 = wm * 16;
    const int nrow0 = wn * 64;

    float c[8][4];
    #pragma unroll
    for (int b = 0; b < 8; b++)
        #pragma unroll
        for (int d = 0; d < 4; d++) c[b][d] = 0.f;

    V_LOAD(0, 0u);
    V_LOAD(1, (unsigned)STAGE_B);

    for (int ch = 0; ch < 64; ch++) {
        const unsigned st = (unsigned)((ch % 3) * STAGE_B);
        if (ch + 2 < 64) { V_LOAD(ch + 2, (unsigned)(((ch + 2) % 3) * STAGE_B)); CP_WAIT2(); }
        else if (ch + 1 < 64) { CP_WAIT1(); }
        else { CP_WAIT0(); }
        __syncthreads();

        #pragma unroll
        for (int ks = 0; ks < 2; ks++) {
            const int kg0 = ks * 2;
            unsigned ah[4], al[4], bh[4][4], bl[4][4];
            lda_frag(sbase + st, mrow0, ks, g, t2, ah, al);
            #pragma unroll
            for (int np = 0; np < 4; np++) {
                unsigned aB = ldsm_addr(sbase + st + BH_OFF, nrow0 + np*16, kg0, lane);
                unsigned aC = ldsm_addr(sbase + st + BL_OFF, nrow0 + np*16, kg0, lane);
                ldsm4(bh[np][0], bh[np][1], bh[np][2], bh[np][3], aB);
                ldsm4(bl[np][0], bl[np][1], bl[np][2], bl[np][3], aC);
            }
            #pragma unroll
            for (int np = 0; np < 4; np++) {
                mma16816(c[np*2],   ah, bh[np][0], bh[np][2]);
                mma16816(c[np*2],   ah, bl[np][0], bl[np][2]);
                mma16816(c[np*2],   al, bh[np][0], bh[np][2]);
                mma16816(c[np*2+1], ah, bh[np][1], bh[np][3]);
                mma16816(c[np*2+1], ah, bl[np][1], bl[np][3]);
                mma16816(c[np*2+1], al, bh[np][1], bh[np][3]);
            }
        }
        __syncthreads();
    }

    {
        int mA = m0 + mrow0 + g;
        #pragma unroll
        for (int nt = 0; nt < 8; nt++) {
            int col = nrow0 + nt * 8 + t2 * 2;
            unsigned h, l;
            packhl(c[nt][0], c[nt][1], h, l);
            *(unsigned*)&g_Vh[(size_t)mA * HD + col] = h;
            *(unsigned*)&g_Vl[(size_t)mA * HD + col] = l;
            packhl(c[nt][2], c[nt][3], h, l);
            *(unsigned*)&g_Vh[(size_t)(mA + 8) * HD + col] = h;
            *(unsigned*)&g_Vl[(size_t)(mA + 8) * HD + col] = l;
        }
    }
}

// ---------------------------------------------------------------------------
// Flash attention: S via single-product tf32 (Q,K fp32/tf32 in smem),
// P.V via bf16 3-product (unchanged). Pipelined K/V commit groups.
// smem: Q 64x528 | K 64x528 | Vh 16K | Vl 16K = 100352B -> 2 CTAs/SM.
// ---------------------------------------------------------------------------
#define FQ  0
#define FK  33792
#define FVH 67584
#define FVL 83968
#define FLASH_SMEM 100352
#define NTASKS (Bn * (Tn/64))    // 256

__device__ __forceinline__ unsigned faddr(unsigned base, int row0, int g0, int lane) {
    int r = row0 + (lane & 7) + ((lane >> 3) & 1) * 8;
    int g = g0 + (lane >> 4);
    return base + r * 256 + (((unsigned)(g ^ (r & 7))) << 4);
}

__global__ __launch_bounds__(128, 2) void flash_kernel(float* __restrict__ out)
{
    extern __shared__ char fsm[];
    __shared__ int t_sh;
    const unsigned sb = smem_u32(fsm);
    const int tid  = threadIdx.x;
    const int wid  = tid >> 5;
    const int lane = tid & 31;
    const int g    = lane >> 2;
    const int t2   = lane & 3;

    // K loader: 64 rows x 32 granules fp32 (row stride 528B)
    #define LOAD_K(b, k0)                                                       \
    {                                                                           \
        _Pragma("unroll")                                                       \
        for (int q = 0; q < 16; q++) {                                          \
            int u = tid + q * 128;                                              \
            int r = u >> 5, gg = u & 31;                                        \
            CP16(sb + FK + r * 528 + gg * 16,                                   \
                 g_K + ((size_t)((b)*Tn + (k0) + r)) * HD + gg * 4);            \
        }                                                                       \
        CP_COMMIT();                                                            \
    }
    // V loader: bf16 hi/lo, swizzled 256B rows (unchanged)
    #define LOAD_V(b, k0)                                                       \
    {                                                                           \
        _Pragma("unroll")                                                       \
        for (int q = 0; q < 8; q++) {                                           \
            int u = tid + q * 128;                                              \
            int r = u >> 4, gg = u & 15;                                        \
            unsigned d = r * 256 + (((unsigned)(gg ^ (r & 7))) << 4);           \
            size_t ko = ((size_t)((b)*Tn + (k0) + r)) * HD + gg * 8;            \
            CP16(sb + FVH + d, g_Vh + ko);                                      \
            CP16(sb + FVL + d, g_Vl + ko);                                      \
        }                                                                       \
        CP_COMMIT();                                                            \
    }

    while (true) {
        if (tid == 0) t_sh = atomicAdd(&g_ctr, 1);
        __syncthreads();
        const int task = t_sh;
        if (task >= NTASKS) break;
        const int b  = task & 3;
        const int qt = 63 - (task >> 2);      // heavy-first (LPT)
        const int q0 = qt * 64;

        // group 1: Q + K(0); group 2: V(0)
        #pragma unroll
        for (int q = 0; q < 16; q++) {
            int u = tid + q * 128;
            int r = u >> 5, gg = u & 31;
            CP16(sb + FQ + r * 528 + gg * 16,
                 g_Q + ((size_t)(b*Tn + q0 + r)) * HD + gg * 4);
            CP16(sb + FK + r * 528 + gg * 16,
                 g_K + ((size_t)(b*Tn + r)) * HD + gg * 4);
        }
        CP_COMMIT();
        LOAD_V(b, 0);

        float o[16][4];
        #pragma unroll
        for (int i = 0; i < 16; i++)
            #pragma unroll
            for (int j = 0; j < 4; j++) o[i][j] = 0.f;
        float m_st[2] = {-1e30f, -1e30f};
        float l_st[2] = {0.f, 0.f};

        for (int kt = 0; kt <= qt; kt++) {
            CP_WAIT1();              // K(kt) (and Q) complete
            __syncthreads();

            // ---- S = Q K^T, single tf32 product (Q carries 1/sqrt(C)) ----
            float c[8][4];
            #pragma unroll
            for (int i = 0; i < 8; i++)
                #pragma unroll
                for (int j = 0; j < 4; j++) c[i][j] = 0.f;

            #pragma unroll
            for (int kc = 0; kc < 16; kc++) {
                unsigned a[4];
                {
                    unsigned ab = sb + FQ + (unsigned)(16*wid + g) * 528
                                + (unsigned)kc * 32 + (unsigned)t2 * 4;
                    asm volatile("ld.shared.b32 %0, [%1];" : "=r"(a[0]) : "r"(ab));
                    asm volatile("ld.shared.b32 %0, [%1];" : "=r"(a[1]) : "r"(ab + 8*528));
                    asm volatile("ld.shared.b32 %0, [%1];" : "=r"(a[2]) : "r"(ab + 16));
                    asm volatile("ld.shared.b32 %0, [%1];" : "=r"(a[3]) : "r"(ab + 8*528 + 16));
                }
                #pragma unroll
                for (int np = 0; np < 8; np++) {
                    unsigned bb = sb + FK + (unsigned)(np*8 + g) * 528
                                + (unsigned)kc * 32 + (unsigned)t2 * 4;
                    unsigned b0, b1;
                    asm volatile("ld.shared.b32 %0, [%1];" : "=r"(b0) : "r"(bb));
                    asm volatile("ld.shared.b32 %0, [%1];" : "=r"(b1) : "r"(bb + 16));
                    mma1688t(c[np], a, b0, b1);
                }
            }

            // ---- causal mask (diagonal tile only) ----
            if (kt == qt) {
                const int r0 = 16*wid + g, r1 = r0 + 8;
                #pragma unroll
                for (int nt = 0; nt < 8; nt++) {
                    int cb = 8*nt + 2*t2;
                    if (cb     > r0) c[nt][0] = -1e30f;
                    if (cb + 1 > r0) c[nt][1] = -1e30f;
                    if (cb     > r1) c[nt][2] = -1e30f;
                    if (cb + 1 > r1) c[nt][3] = -1e30f;
                }
            }

            // ---- online softmax on fragments (quad shfl) ----
            float corr[2];
            #pragma unroll
            for (int h = 0; h < 2; h++) {
                float mx = -1e30f;
                #pragma unroll
                for (int nt = 0; nt < 8; nt++)
                    mx = fmaxf(mx, fmaxf(c[nt][2*h], c[nt][2*h+1]));
                mx = fmaxf(mx, __shfl_xor_sync(0xffffffffu, mx, 1));
                mx = fmaxf(mx, __shfl_xor_sync(0xffffffffu, mx, 2));
                float mn = fmaxf(m_st[h], mx);
                corr[h] = __expf(m_st[h] - mn);
                m_st[h] = mn;
                float sum = 0.f;
                #pragma unroll
                for (int nt = 0; nt < 8; nt++) {
                    float p0 = __expf(c[nt][2*h]   - mn);
                    float p1 = __expf(c[nt][2*h+1] - mn);
                    c[nt][2*h] = p0; c[nt][2*h+1] = p1;
                    sum += p0 + p1;
                }
                sum += __shfl_xor_sync(0xffffffffu, sum, 1);
                sum += __shfl_xor_sync(0xffffffffu, sum, 2);
                l_st[h] = l_st[h] * corr[h] + sum;
            }

            CP_WAIT0();              // V(kt) complete
            __syncthreads();         // all warps past K reads
            if (kt < qt) LOAD_K(b, (kt + 1) * 64);   // prefetch K during PV

            // ---- rescale O ----
            #pragma unroll
            for (int nt = 0; nt < 16; nt++) {
                o[nt][0] *= corr[0]; o[nt][1] *= corr[0];
                o[nt][2] *= corr[1]; o[nt][3] *= corr[1];
            }

            // ---- P -> bf16 hi/lo A-fragments ----
            unsigned ph[4][4], pl[4][4];
            #pragma unroll
            for (int k2 = 0; k2 < 4; k2++) {
                #pragma unroll
                for (int j = 0; j < 4; j++) {
                    int nt = 2*k2 + (j >> 1);
                    float p0 = c[nt][(j & 1) * 2];
                    float p1 = c[nt][(j & 1) * 2 + 1];
                    float h0 = __bfloat162float(__float2bfloat16(p0));
                    float h1 = __bfloat162float(__float2bfloat16(p1));
                    ph[k2][j] = packbf(p0, p1);
                    pl[k2][j] = packbf(p0 - h0, p1 - h1);
                }
            }

            // ---- O += P V  (bf16, 3 products) ----
            #pragma unroll
            for (int np = 0; np < 8; np++) {
                #pragma unroll
                for (int k2 = 0; k2 < 4; k2++) {
                    unsigned vh[4], vl[4];
                    ldsm4t(vh[0], vh[1], vh[2], vh[3], faddr(sb + FVH, 16*k2, 2*np, lane));
                    ldsm4t(vl[0], vl[1], vl[2], vl[3], faddr(sb + FVL, 16*k2, 2*np, lane));
                    mma16816(o[2*np],   ph[k2], vh[0], vh[1]);
                    mma16816(o[2*np],   ph[k2], vl[0], vl[1]);
                    mma16816(o[2*np],   pl[k2], vh[0], vh[1]);
                    mma16816(o[2*np+1], ph[k2], vh[2], vh[3]);
                    mma16816(o[2*np+1], ph[k2], vl[2], vl[3]);
                    mma16816(o[2*np+1], pl[k2], vh[2], vh[3]);
                }
            }

            __syncthreads();         // all warps past V reads
            if (kt < qt) LOAD_V(b, (kt + 1) * 64);   // prefetch V during next S
        }

        // ---- normalize & write ----
        {
            float i0 = 1.f / l_st[0], i1 = 1.f / l_st[1];
            int r0 = q0 + 16*wid + g;
            #pragma unroll
            for (int nt = 0; nt < 16; nt++) {
                int col = 8*nt + 2*t2;
                *(float2*)&out[((size_t)b*Tn + r0)     * HD + col] =
                    make_float2(o[nt][0]*i0, o[nt][1]*i0);
                *(float2*)&out[((size_t)b*Tn + r0 + 8) * HD + col] =
                    make_float2(o[nt][2]*i1, o[nt][3]*i1);
            }
        }
    }
}

// ---------------------------------------------------------------------------
extern "C" void kernel_launch(void* const* d_in, const int* in_sizes, int n_in,
                              void* d_out, int out_size)
{
    const float* x  = (const float*)d_in[0];
    const float* Wq = (const float*)d_in[1];
    const float* Wk = (const float*)d_in[2];
    const float* Wv = (const float*)d_in[3];
    const float* cs = (const float*)d_in[4];
    const float* sn = (const float*)d_in[5];
    float* out = (float*)d_out;

    cudaFuncSetAttribute(gemm_qk_kernel,
                         cudaFuncAttributeMaxDynamicSharedMemorySize, QK_SMEM);
    cudaFuncSetAttribute(gemm_v_kernel,
                         cudaFuncAttributeMaxDynamicSharedMemorySize, V_SMEM);
    cudaFuncSetAttribute(flash_kernel,
                         cudaFuncAttributeMaxDynamicSharedMemorySize, FLASH_SMEM);

    wsplit_kernel<<<(3*NW4 + 255)/256, 256>>>(Wq, Wk, Wv);
    gemm_qk_kernel<<<dim3(2, Mn/64), 256, QK_SMEM>>>(x, cs, sn);
    gemm_v_kernel<<<dim3(1, Mn/64), 256, V_SMEM>>>(x);
    flash_kernel<<<296, 128, FLASH_SMEM>>>(out);
}